// round 8
// baseline (speedup 1.0000x reference)
#include <cuda_runtime.h>
#include <cuda_bf16.h>
#include <math.h>
#include <stdint.h>

// ---------------------------------------------------------------------------
// Problem constants
// ---------------------------------------------------------------------------
#define BB   64
#define SS   32
#define HH   1024
#define RR   256
#define DEPTH 9
#define MAXM (BB*512)

#define SELU_SCALE 1.0507009873554805f
#define SELU_ALPHA 1.6732632423543772f

__device__ __forceinline__ float seluf(float v) {
    return v > 0.f ? SELU_SCALE * v : SELU_SCALE * SELU_ALPHA * expm1f(v);
}
__device__ __forceinline__ float sigmoidf_(float v) {
    return 1.f / (1.f + __expf(-v));
}

// quantize v (already divided by scale: t = v/s) into q1*128 + q2
__device__ __forceinline__ uint32_t pack4(int a, int b, int c, int d) {
    return (uint32_t)(uint8_t)(int8_t)a | ((uint32_t)(uint8_t)(int8_t)b << 8)
         | ((uint32_t)(uint8_t)(int8_t)c << 16) | ((uint32_t)(uint8_t)(int8_t)d << 24);
}
__device__ __forceinline__ void quant2(float t, int& i1, int& i2) {
    i1 = __float2int_rn(t * 0.0078125f);
    i1 = max(-127, min(127, i1));
    i2 = __float2int_rn(t - 128.f * (float)i1);
    i2 = max(-127, min(127, i2));
}

// ---------------------------------------------------------------------------
// Scratch (device globals; allocation is forbidden)
// ---------------------------------------------------------------------------
__device__ float g_xcA[(size_t)MAXM * HH];
__device__ float g_xcB[(size_t)MAXM * HH];
__device__ float g_hcA[(size_t)MAXM * RR];
__device__ float g_hcB[(size_t)MAXM * RR];
__device__ float g_dA[MAXM];
__device__ float g_dB[MAXM];
__device__ float g_gi[(size_t)MAXM * 3 * RR];
__device__ float g_gh[(size_t)MAXM * 3 * RR];
__device__ float g_y [(size_t)BB * SS * HH];
__device__ float g_lr[(size_t)MAXM * HH];        // branch out viewed [2M,1024]
// int8 slices + scales
__device__ int8_t g_sxq1[(size_t)BB * SS * HH];
__device__ int8_t g_sxq2[(size_t)BB * SS * HH];
__device__ float  g_sxs[BB * SS];
__device__ int8_t g_xcq1[(size_t)MAXM * HH];
__device__ int8_t g_xcq2[(size_t)MAXM * HH];
__device__ float  g_xcs[MAXM];
__device__ int8_t g_hcq1A[(size_t)MAXM * RR];
__device__ int8_t g_hcq2A[(size_t)MAXM * RR];
__device__ float  g_hcsA[MAXM];
__device__ int8_t g_hcq1B[(size_t)MAXM * RR];
__device__ int8_t g_hcq2B[(size_t)MAXM * RR];
__device__ float  g_hcsB[MAXM];
__device__ int8_t g_xhq1[(size_t)MAXM * (HH + RR)];
__device__ int8_t g_xhq2[(size_t)MAXM * (HH + RR)];
__device__ float  g_xhs[MAXM];
__device__ int8_t g_lrq1[(size_t)MAXM * HH];
__device__ int8_t g_lrq2[(size_t)MAXM * HH];
__device__ float  g_lrqs[MAXM];
// weight slices
__device__ int8_t g_wihq1[3*RR*HH];
__device__ int8_t g_wihq2[3*RR*HH];
__device__ float  g_wihs[3*RR];
__device__ int8_t g_whhq1[3*RR*RR];
__device__ int8_t g_whhq2[3*RR*RR];
__device__ float  g_whhs[3*RR];
__device__ int8_t g_wbrq1[2*HH*(HH+RR)];
__device__ int8_t g_wbrq2[2*HH*(HH+RR)];
__device__ float  g_wbrs[2*HH];
__device__ int8_t g_whidq1[HH*HH];
__device__ int8_t g_whidq2[HH*HH];
__device__ float  g_whids[HH];

// ---------------------------------------------------------------------------
// mma / smem helpers
// ---------------------------------------------------------------------------
__device__ __forceinline__ void ldsm4(uint32_t* r, uint32_t a) {
    asm volatile("ldmatrix.sync.aligned.m8n8.x4.shared.b16 {%0,%1,%2,%3}, [%4];"
        : "=r"(r[0]), "=r"(r[1]), "=r"(r[2]), "=r"(r[3]) : "r"(a));
}
__device__ __forceinline__ void mma_s8(int* d, const uint32_t* a, uint32_t b0, uint32_t b1) {
    asm volatile("mma.sync.aligned.m16n8k32.row.col.s32.s8.s8.s32 "
        "{%0,%1,%2,%3}, {%4,%5,%6,%7}, {%8,%9}, {%0,%1,%2,%3};"
        : "+r"(d[0]), "+r"(d[1]), "+r"(d[2]), "+r"(d[3])
        : "r"(a[0]), "r"(a[1]), "r"(a[2]), "r"(a[3]), "r"(b0), "r"(b1));
}
__device__ __forceinline__ void cpa16(uint32_t dst, const void* src, int srcsize) {
    asm volatile("cp.async.cg.shared.global [%0], [%1], 16, %2;"
                 :: "r"(dst), "l"(src), "r"(srcsize));
}
__device__ __forceinline__ uint32_t smem_u32(const void* p) {
    return (uint32_t)__cvta_generic_to_shared(p);
}

// ---------------------------------------------------------------------------
// int8 dual-slice GEMM: C = epi( sA[r]*sW[c]*(16384*Hi + 128*Mid) + bias )
//   Hi = q1a.q1w ; Mid = q1a.q2w + q2a.q1w
// 128x128 CTA tile, 512 threads, 16 warps of 32x32. BK = 128 bytes.
// Stage = {A1,A2,W1,W2} x 128x128B = 64 KB; 3 stages = 192 KB.
//   EPI 0: none   EPI 1: selu   EPI 2: P[r>>1] - selu
// Requires N % 128 == 0, K % 128 == 0.
// ---------------------------------------------------------------------------
#define IG_STAGE 65536
#define IG_DYNSMEM (3 * IG_STAGE)

template<int EPI>
__global__ __launch_bounds__(512, 1)
void igemm(const int8_t* __restrict__ Aq1, const int8_t* __restrict__ Aq2,
           const float* __restrict__ As,
           const int8_t* __restrict__ Wq1, const int8_t* __restrict__ Wq2,
           const float* __restrict__ Ws,
           const float* __restrict__ bias, float* __restrict__ Cf,
           int M, int N, int K, const float* __restrict__ P)
{
    extern __shared__ char dynsm[];
    const uint32_t smBase = smem_u32(dynsm);

    const int tid = threadIdx.x;
    const int warp = tid >> 5, lane = tid & 31;
    const int wm = warp >> 2, wn = warp & 3;          // 4x4 warp grid, 32x32 tiles
    const int row0 = blockIdx.y * 128, col0 = blockIdx.x * 128;

    const int T = K >> 7;                              // 128-byte k-tiles

    int accHi[2][4][4], accMid[2][4][4];
    #pragma unroll
    for (int a = 0; a < 2; a++)
        #pragma unroll
        for (int b = 0; b < 4; b++)
            #pragma unroll
            for (int c = 0; c < 4; c++) { accHi[a][b][c] = 0; accMid[a][b][c] = 0; }

    // ---- load geometry: 4 threads/row, 2 chunks each per tile ----
    const int lrow = tid >> 2;                         // 0..127
    const int lc0  = (tid & 3) * 2;
    const int grA  = row0 + lrow;
    const int okA  = (grA < M) ? 16 : 0;
    const size_t offA = (size_t)((grA < M) ? grA : 0) * K;
    const size_t offW = (size_t)(col0 + lrow) * K;
    const uint32_t sRowBase = lrow * 128;

    auto load_stage = [&](int it, int buf) {
        const int k0 = it << 7;
        const uint32_t sb = smBase + buf * IG_STAGE;
        #pragma unroll
        for (int j = 0; j < 2; j++) {
            int c = lc0 + j;
            uint32_t sw = sRowBase + (uint32_t)((c ^ (lrow & 7)) << 4);
            cpa16(sb +         sw, Aq1 + offA + k0 + c * 16, okA);
            cpa16(sb + 16384 + sw, Aq2 + offA + k0 + c * 16, okA);
            cpa16(sb + 32768 + sw, Wq1 + offW + k0 + c * 16, 16);
            cpa16(sb + 49152 + sw, Wq2 + offW + k0 + c * 16, 16);
        }
        asm volatile("cp.async.commit_group;" ::: "memory");
    };

    load_stage(0, 0);
    if (T > 1) load_stage(1, 1);

    // ---- fragment addressing ----
    const int aRow = wm * 32 + (lane & 15);            // + mt*16
    const int aChk = (lane >> 4);
    const int bRow = wn * 32 + (lane & 7) + ((lane >> 4) << 3);  // + p*16
    const int bChk = ((lane >> 3) & 1);

    for (int it = 0; it < T; ++it) {
        if (it + 1 < T) { asm volatile("cp.async.wait_group 1;" ::: "memory"); }
        else            { asm volatile("cp.async.wait_group 0;" ::: "memory"); }
        __syncthreads();

        if (it + 2 < T) load_stage(it + 2, (it + 2) % 3);

        const uint32_t sb = smBase + (it % 3) * IG_STAGE;
        #pragma unroll
        for (int s = 0; s < 4; s++) {                  // four k32 steps
            uint32_t a1f[2][4], a2f[2][4], w1f[2][4], w2f[2][4];
            #pragma unroll
            for (int mt = 0; mt < 2; mt++) {
                int r = aRow + mt * 16;
                uint32_t col = (uint32_t)(((s * 2 + aChk) ^ (r & 7)) << 4);
                ldsm4(a1f[mt], sb +         r * 128 + col);
                ldsm4(a2f[mt], sb + 16384 + r * 128 + col);
            }
            #pragma unroll
            for (int p = 0; p < 2; p++) {
                int r = bRow + p * 16;
                uint32_t col = (uint32_t)(((s * 2 + bChk) ^ (r & 7)) << 4);
                ldsm4(w1f[p], sb + 32768 + r * 128 + col);
                ldsm4(w2f[p], sb + 49152 + r * 128 + col);
            }
            #pragma unroll
            for (int mt = 0; mt < 2; mt++)
                #pragma unroll
                for (int q = 0; q < 4; q++) {
                    uint32_t b10 = w1f[q >> 1][(q & 1) * 2], b11 = w1f[q >> 1][(q & 1) * 2 + 1];
                    uint32_t b20 = w2f[q >> 1][(q & 1) * 2], b21 = w2f[q >> 1][(q & 1) * 2 + 1];
                    mma_s8(accHi [mt][q], a1f[mt], b10, b11);
                    mma_s8(accMid[mt][q], a1f[mt], b20, b21);
                    mma_s8(accMid[mt][q], a2f[mt], b10, b11);
                }
        }
    }

    // ---- epilogue ----
    const int g = lane >> 2, t4 = lane & 3;
    #pragma unroll
    for (int mt = 0; mt < 2; mt++) {
        #pragma unroll
        for (int half = 0; half < 2; half++) {
            int r = row0 + wm * 32 + mt * 16 + g + half * 8;
            if (r >= M) continue;
            float sa = As[r];
            #pragma unroll
            for (int q = 0; q < 4; q++) {
                int c = col0 + wn * 32 + q * 8 + (t4 << 1);
                float2 sw2 = *(const float2*)(Ws + c);
                float2 bv  = *(const float2*)(bias + c);
                float f0 = 16384.f * (float)accHi[mt][q][half * 2 + 0]
                         +   128.f * (float)accMid[mt][q][half * 2 + 0];
                float f1 = 16384.f * (float)accHi[mt][q][half * 2 + 1]
                         +   128.f * (float)accMid[mt][q][half * 2 + 1];
                float v0 = sa * sw2.x * f0 + bv.x;
                float v1 = sa * sw2.y * f1 + bv.y;
                if (EPI == 1) { v0 = seluf(v0); v1 = seluf(v1); }
                if (EPI == 2) {
                    float2 p = *(const float2*)(P + (size_t)(r >> 1) * HH + c);
                    v0 = p.x - seluf(v0);
                    v1 = p.y - seluf(v1);
                }
                *(float2*)(Cf + (size_t)r * N + c) = make_float2(v0, v1);
            }
        }
    }
}

// ---------------------------------------------------------------------------
// Quantization / elementwise kernels
// ---------------------------------------------------------------------------
// generic per-row quantizer: block(256) per row, K % 4 == 0, K <= 2048.
// DOSELU: apply selu before quantizing (no fp32 output stored).
template<bool DOSELU>
__global__ void rowquant_kernel(const float* __restrict__ src, int8_t* __restrict__ q1,
                                int8_t* __restrict__ q2, float* __restrict__ sc, int K) {
    const int row = blockIdx.x, tid = threadIdx.x;
    const float* s = src + (size_t)row * K;
    __shared__ float red[256];
    __shared__ float s_inv;
    float4 buf[2];
    const int nch = K >> 2;
    float m = 0.f;
    int cnt = 0;
    for (int c = tid; c < nch; c += 256) {
        float4 v = ((const float4*)s)[c];
        if (DOSELU) { v.x = seluf(v.x); v.y = seluf(v.y); v.z = seluf(v.z); v.w = seluf(v.w); }
        buf[cnt++] = v;
        m = fmaxf(m, fmaxf(fmaxf(fabsf(v.x), fabsf(v.y)), fmaxf(fabsf(v.z), fabsf(v.w))));
    }
    red[tid] = m;
    __syncthreads();
    #pragma unroll
    for (int o = 128; o; o >>= 1) {
        if (tid < o) red[tid] = fmaxf(red[tid], red[tid + o]);
        __syncthreads();
    }
    if (tid == 0) {
        float sv = fmaxf(red[0], 1e-30f) * (1.f / 16256.f);
        sc[row] = sv;
        s_inv = 1.f / sv;
    }
    __syncthreads();
    const float inv = s_inv;
    cnt = 0;
    for (int c = tid; c < nch; c += 256) {
        float4 v = buf[cnt++];
        int a1, a2, b1, b2, c1, c2, d1, d2;
        quant2(v.x * inv, a1, a2); quant2(v.y * inv, b1, b2);
        quant2(v.z * inv, c1, c2); quant2(v.w * inv, d1, d2);
        ((uint32_t*)(q1 + (size_t)row * K))[c] = pack4(a1, b1, c1, d1);
        ((uint32_t*)(q2 + (size_t)row * K))[c] = pack4(a2, b2, c2, d2);
    }
}

// y[64,32,1024] -> xc fp32 [64,1024] + slices; block per batch row
__global__ void mean_quant_kernel(const float* __restrict__ y, float* __restrict__ xc,
                                  int8_t* __restrict__ q1, int8_t* __restrict__ q2,
                                  float* __restrict__ sc) {
    const int b = blockIdx.x, tid = threadIdx.x;   // 256 threads, chunk = tid
    __shared__ float red[256];
    __shared__ float s_inv;
    float4 acc = make_float4(0.f, 0.f, 0.f, 0.f);
    const float4* yb = (const float4*)(y + (size_t)b * SS * HH);
    #pragma unroll 8
    for (int t = 0; t < SS; t++) {
        float4 v = yb[t * (HH / 4) + tid];
        acc.x += v.x; acc.y += v.y; acc.z += v.z; acc.w += v.w;
    }
    acc.x *= (1.f / SS); acc.y *= (1.f / SS); acc.z *= (1.f / SS); acc.w *= (1.f / SS);
    ((float4*)(xc + (size_t)b * HH))[tid] = acc;
    float m = fmaxf(fmaxf(fabsf(acc.x), fabsf(acc.y)), fmaxf(fabsf(acc.z), fabsf(acc.w)));
    red[tid] = m;
    __syncthreads();
    #pragma unroll
    for (int o = 128; o; o >>= 1) {
        if (tid < o) red[tid] = fmaxf(red[tid], red[tid + o]);
        __syncthreads();
    }
    if (tid == 0) {
        float sv = fmaxf(red[0], 1e-30f) * (1.f / 16256.f);
        sc[b] = sv;
        s_inv = 1.f / sv;
    }
    __syncthreads();
    const float inv = s_inv;
    int a1, a2, b1, b2, c1, c2, d1, d2;
    quant2(acc.x * inv, a1, a2); quant2(acc.y * inv, b1, b2);
    quant2(acc.z * inv, c1, c2); quant2(acc.w * inv, d1, d2);
    ((uint32_t*)(q1 + (size_t)b * HH))[tid] = pack4(a1, b1, c1, d1);
    ((uint32_t*)(q2 + (size_t)b * HH))[tid] = pack4(a2, b2, c2, d2);
}

// GRU + per-row quant: warp per row (8 rows / 256-thread block)
__global__ void gru_quant_kernel(const float* __restrict__ gi, const float* __restrict__ gh,
                                 float* __restrict__ hc, int8_t* __restrict__ q1,
                                 int8_t* __restrict__ q2, float* __restrict__ sc, int M) {
    const int m = blockIdx.x * 8 + (threadIdx.x >> 5);
    const int lane = threadIdx.x & 31;
    if (m >= M) return;
    const size_t o = (size_t)m * (3 * RR);
    const size_t ho = (size_t)m * RR;
    float v[8];
    float mx = 0.f;
    #pragma unroll
    for (int u = 0; u < 8; u++) {
        int j = lane + 32 * u;
        float ir = gi[o + j], iz = gi[o + RR + j], inn = gi[o + 2 * RR + j];
        float hr = gh[o + j], hz = gh[o + RR + j], hn  = gh[o + 2 * RR + j];
        float r = sigmoidf_(ir + hr);
        float z = sigmoidf_(iz + hz);
        float n = tanhf(inn + r * hn);
        float nv = (1.f - z) * n + z * hc[ho + j];
        v[u] = nv;
        hc[ho + j] = nv;
        mx = fmaxf(mx, fabsf(nv));
    }
    #pragma unroll
    for (int off = 16; off; off >>= 1) mx = fmaxf(mx, __shfl_xor_sync(0xffffffffu, mx, off));
    float sv = fmaxf(mx, 1e-30f) * (1.f / 16256.f);
    if (lane == 0) sc[m] = sv;
    const float inv = 1.f / sv;
    #pragma unroll
    for (int u = 0; u < 8; u++) {
        int j = lane + 32 * u;
        int i1, i2;
        quant2(v[u] * inv, i1, i2);
        q1[ho + j] = (int8_t)i1;
        q2[ho + j] = (int8_t)i2;
    }
}

// xh = [xc | hc] quantized rows of 1280; block(256) per row
__global__ void xh_quant_kernel(const float* __restrict__ xc, const float* __restrict__ hc,
                                int8_t* __restrict__ q1, int8_t* __restrict__ q2,
                                float* __restrict__ sc) {
    const int m = blockIdx.x, tid = threadIdx.x;
    __shared__ float red[256];
    __shared__ float s_inv;
    float4 vx = ((const float4*)(xc + (size_t)m * HH))[tid];
    float4 vh = make_float4(0.f, 0.f, 0.f, 0.f);
    if (tid < 64) vh = ((const float4*)(hc + (size_t)m * RR))[tid];
    float mx = fmaxf(fmaxf(fabsf(vx.x), fabsf(vx.y)), fmaxf(fabsf(vx.z), fabsf(vx.w)));
    mx = fmaxf(mx, fmaxf(fmaxf(fabsf(vh.x), fabsf(vh.y)), fmaxf(fabsf(vh.z), fabsf(vh.w))));
    red[tid] = mx;
    __syncthreads();
    #pragma unroll
    for (int o = 128; o; o >>= 1) {
        if (tid < o) red[tid] = fmaxf(red[tid], red[tid + o]);
        __syncthreads();
    }
    if (tid == 0) {
        float sv = fmaxf(red[0], 1e-30f) * (1.f / 16256.f);
        sc[m] = sv;
        s_inv = 1.f / sv;
    }
    __syncthreads();
    const float inv = s_inv;
    const size_t rb = (size_t)m * (HH + RR);
    int a1, a2, b1, b2, c1, c2, d1, d2;
    quant2(vx.x * inv, a1, a2); quant2(vx.y * inv, b1, b2);
    quant2(vx.z * inv, c1, c2); quant2(vx.w * inv, d1, d2);
    ((uint32_t*)(q1 + rb))[tid] = pack4(a1, b1, c1, d1);
    ((uint32_t*)(q2 + rb))[tid] = pack4(a2, b2, c2, d2);
    if (tid < 64) {
        quant2(vh.x * inv, a1, a2); quant2(vh.y * inv, b1, b2);
        quant2(vh.z * inv, c1, c2); quant2(vh.w * inv, d1, d2);
        ((uint32_t*)(q1 + rb + HH))[tid] = pack4(a1, b1, c1, d1);
        ((uint32_t*)(q2 + rb + HH))[tid] = pack4(a2, b2, c2, d2);
    }
}

__global__ void hb_kernel(const float* __restrict__ xc, const float* __restrict__ hc,
                          const float* __restrict__ Whb, const float* __restrict__ bhb,
                          const float* __restrict__ dIn, float* __restrict__ dOut, int M) {
    int w = (blockIdx.x * blockDim.x + threadIdx.x) >> 5;
    int lane = threadIdx.x & 31;
    if (w >= M) return;
    const float4* xr = (const float4*)(xc + (size_t)w * HH);
    const float4* hr = (const float4*)(hc + (size_t)w * RR);
    const float4* w4 = (const float4*)Whb;
    float s = 0.f;
    #pragma unroll 4
    for (int i = lane; i < 256; i += 32) {
        float4 a = xr[i], b = w4[i];
        s += a.x * b.x + a.y * b.y + a.z * b.z + a.w * b.w;
    }
    #pragma unroll 2
    for (int i = lane; i < 64; i += 32) {
        float4 a = hr[i], b = w4[256 + i];
        s += a.x * b.x + a.y * b.y + a.z * b.z + a.w * b.w;
    }
    #pragma unroll
    for (int o = 16; o; o >>= 1) s += __shfl_xor_sync(0xffffffffu, s, o);
    if (lane == 0) dOut[w] = dIn[w] + sigmoidf_(s + bhb[0]);
}

__global__ void repeat_kernel(const float* __restrict__ hcIn, const int8_t* __restrict__ q1In,
                              const int8_t* __restrict__ q2In, const float* __restrict__ sIn,
                              const float* __restrict__ dIn,
                              float* __restrict__ hcOut, int8_t* __restrict__ q1Out,
                              int8_t* __restrict__ q2Out, float* __restrict__ sOut,
                              float* __restrict__ dOut, int M2) {
    int i = blockIdx.x * blockDim.x + threadIdx.x;   // over M2*64
    if (i >= M2 * 64) return;
    int m = i >> 6, j = i & 63;
    int p = m >> 1;
    ((float4*)hcOut)[(size_t)m * 64 + j] = ((const float4*)hcIn)[(size_t)p * 64 + j];
    if (j < 16) {
        ((uint4*)q1Out)[(size_t)m * 16 + j] = ((const uint4*)q1In)[(size_t)p * 16 + j];
        ((uint4*)q2Out)[(size_t)m * 16 + j] = ((const uint4*)q2In)[(size_t)p * 16 + j];
    }
    if (j == 0) { sOut[m] = sIn[p]; dOut[m] = dIn[p]; }
}

__global__ void zero32_kernel(uint32_t* p, int n) {
    int i = blockIdx.x * blockDim.x + threadIdx.x;
    if (i < n) p[i] = 0u;
}
__global__ void setf_kernel(float* p, float v, int n) {
    int i = blockIdx.x * blockDim.x + threadIdx.x;
    if (i < n) p[i] = v;
}

__global__ void out_kernel(const float* __restrict__ xc, const float* __restrict__ dep,
                           float* __restrict__ out) {
    int i = blockIdx.x * blockDim.x + threadIdx.x;
    if (i >= MAXM * (HH + 1)) return;
    int m = i / (HH + 1), k = i - m * (HH + 1);
    out[i] = (k < HH) ? xc[(size_t)m * HH + k] : dep[m];
}

// ---------------------------------------------------------------------------
// Host driver (graph-capturable: only kernel launches)
// ---------------------------------------------------------------------------
static inline int cdiv(int a, int b) { return (a + b - 1) / b; }

extern "C" void kernel_launch(void* const* d_in, const int* in_sizes, int n_in,
                              void* d_out, int out_size)
{
    const float* x        = (const float*)d_in[0];
    const float* W_hidden = (const float*)d_in[1];
    const float* b_hidden = (const float*)d_in[2];
    const float* W_hb     = (const float*)d_in[3];
    const float* b_hb     = (const float*)d_in[4];
    const float* W_branch = (const float*)d_in[5];
    const float* b_branch = (const float*)d_in[6];
    const float* W_ih     = (const float*)d_in[7];
    const float* W_hh     = (const float*)d_in[8];
    const float* b_ih     = (const float*)d_in[9];
    const float* b_hh     = (const float*)d_in[10];

    cudaFuncSetAttribute(igemm<0>, cudaFuncAttributeMaxDynamicSharedMemorySize, IG_DYNSMEM);
    cudaFuncSetAttribute(igemm<1>, cudaFuncAttributeMaxDynamicSharedMemorySize, IG_DYNSMEM);
    cudaFuncSetAttribute(igemm<2>, cudaFuncAttributeMaxDynamicSharedMemorySize, IG_DYNSMEM);

    float *xcA, *xcB, *hcA, *hcB, *dA, *dB, *gi, *gh, *y, *lr;
    int8_t *sxq1, *sxq2, *xcq1, *xcq2, *hcq1A, *hcq2A, *hcq1B, *hcq2B;
    int8_t *xhq1, *xhq2, *lrq1, *lrq2;
    float *sxs, *xcs, *hcsA, *hcsB, *xhs, *lrqs;
    int8_t *wihq1, *wihq2, *whhq1, *whhq2, *wbrq1, *wbrq2, *whidq1, *whidq2;
    float *wihs, *whhs, *wbrs, *whids;

    cudaGetSymbolAddress((void**)&xcA, g_xcA);   cudaGetSymbolAddress((void**)&xcB, g_xcB);
    cudaGetSymbolAddress((void**)&hcA, g_hcA);   cudaGetSymbolAddress((void**)&hcB, g_hcB);
    cudaGetSymbolAddress((void**)&dA,  g_dA);    cudaGetSymbolAddress((void**)&dB,  g_dB);
    cudaGetSymbolAddress((void**)&gi,  g_gi);    cudaGetSymbolAddress((void**)&gh,  g_gh);
    cudaGetSymbolAddress((void**)&y,   g_y);     cudaGetSymbolAddress((void**)&lr,  g_lr);
    cudaGetSymbolAddress((void**)&sxq1, g_sxq1); cudaGetSymbolAddress((void**)&sxq2, g_sxq2);
    cudaGetSymbolAddress((void**)&sxs, g_sxs);
    cudaGetSymbolAddress((void**)&xcq1, g_xcq1); cudaGetSymbolAddress((void**)&xcq2, g_xcq2);
    cudaGetSymbolAddress((void**)&xcs, g_xcs);
    cudaGetSymbolAddress((void**)&hcq1A, g_hcq1A); cudaGetSymbolAddress((void**)&hcq2A, g_hcq2A);
    cudaGetSymbolAddress((void**)&hcsA, g_hcsA);
    cudaGetSymbolAddress((void**)&hcq1B, g_hcq1B); cudaGetSymbolAddress((void**)&hcq2B, g_hcq2B);
    cudaGetSymbolAddress((void**)&hcsB, g_hcsB);
    cudaGetSymbolAddress((void**)&xhq1, g_xhq1); cudaGetSymbolAddress((void**)&xhq2, g_xhq2);
    cudaGetSymbolAddress((void**)&xhs, g_xhs);
    cudaGetSymbolAddress((void**)&lrq1, g_lrq1); cudaGetSymbolAddress((void**)&lrq2, g_lrq2);
    cudaGetSymbolAddress((void**)&lrqs, g_lrqs);
    cudaGetSymbolAddress((void**)&wihq1, g_wihq1); cudaGetSymbolAddress((void**)&wihq2, g_wihq2);
    cudaGetSymbolAddress((void**)&wihs, g_wihs);
    cudaGetSymbolAddress((void**)&whhq1, g_whhq1); cudaGetSymbolAddress((void**)&whhq2, g_whhq2);
    cudaGetSymbolAddress((void**)&whhs, g_whhs);
    cudaGetSymbolAddress((void**)&wbrq1, g_wbrq1); cudaGetSymbolAddress((void**)&wbrq2, g_wbrq2);
    cudaGetSymbolAddress((void**)&wbrs, g_wbrs);
    cudaGetSymbolAddress((void**)&whidq1, g_whidq1); cudaGetSymbolAddress((void**)&whidq2, g_whidq2);
    cudaGetSymbolAddress((void**)&whids, g_whids);

    // ---- weight quantization ----
    rowquant_kernel<false><<<3*RR, 256>>>(W_ih, wihq1, wihq2, wihs, HH);
    rowquant_kernel<false><<<3*RR, 256>>>(W_hh, whhq1, whhq2, whhs, RR);
    rowquant_kernel<false><<<2*HH, 256>>>(W_branch, wbrq1, wbrq2, wbrs, HH+RR);
    rowquant_kernel<false><<<HH, 256>>>(W_hidden, whidq1, whidq2, whids, HH);

    // ---- root ----
    rowquant_kernel<true><<<BB*SS, 256>>>(x, sxq1, sxq2, sxs, HH);
    igemm<1><<<dim3(HH/128, (BB*SS)/128), 512, IG_DYNSMEM>>>(
        sxq1, sxq2, sxs, whidq1, whidq2, whids, b_hidden, y, BB*SS, HH, HH, nullptr);
    mean_quant_kernel<<<BB, 256>>>(y, xcA, xcq1, xcq2, xcs);

    zero32_kernel<<<cdiv(BB*RR, 256), 256>>>((uint32_t*)hcA, BB*RR);
    zero32_kernel<<<cdiv(BB*RR/4, 256), 256>>>((uint32_t*)hcq1A, BB*RR/4);
    zero32_kernel<<<cdiv(BB*RR/4, 256), 256>>>((uint32_t*)hcq2A, BB*RR/4);
    setf_kernel<<<1, 64>>>(hcsA, 1.f, BB);
    zero32_kernel<<<1, 64>>>((uint32_t*)dA, BB);

    // ---- levels 0 .. DEPTH-1 ----
    for (int d = 0; d < DEPTH; d++) {
        int M  = BB << d;
        int M2 = M << 1;
        int gy = cdiv(M, 128);

        igemm<0><<<dim3(768/128, gy), 512, IG_DYNSMEM>>>(
            xcq1, xcq2, xcs, wihq1, wihq2, wihs, b_ih, gi, M, 768, HH, nullptr);
        igemm<0><<<dim3(768/128, gy), 512, IG_DYNSMEM>>>(
            hcq1A, hcq2A, hcsA, whhq1, whhq2, whhs, b_hh, gh, M, 768, RR, nullptr);
        gru_quant_kernel<<<cdiv(M, 8), 256>>>(gi, gh, hcA, hcq1A, hcq2A, hcsA, M);

        hb_kernel<<<cdiv(M*32, 256), 256>>>(xcA, hcA, W_hb, b_hb, dA, dA, M);
        xh_quant_kernel<<<M, 256>>>(xcA, hcA, xhq1, xhq2, xhs);

        igemm<1><<<dim3(2*HH/128, gy), 512, IG_DYNSMEM>>>(
            xhq1, xhq2, xhs, wbrq1, wbrq2, wbrs, b_branch, lr, M, 2*HH, HH+RR, nullptr);
        rowquant_kernel<false><<<M2, 256>>>(lr, lrq1, lrq2, lrqs, HH);

        igemm<2><<<dim3(HH/128, cdiv(M2, 128)), 512, IG_DYNSMEM>>>(
            lrq1, lrq2, lrqs, whidq1, whidq2, whids, b_hidden, xcB, M2, HH, HH, xcA);
        rowquant_kernel<false><<<M2, 256>>>(xcB, xcq1, xcq2, xcs, HH);

        repeat_kernel<<<cdiv(M2*64, 256), 256>>>(hcA, hcq1A, hcq2A, hcsA, dA,
                                                 hcB, hcq1B, hcq2B, hcsB, dB, M2);

        float* t; int8_t* bt;
        t = xcA; xcA = xcB; xcB = t;
        t = hcA; hcA = hcB; hcB = t;
        t = dA;  dA  = dB;  dB  = t;
        bt = hcq1A; hcq1A = hcq1B; hcq1B = bt;
        bt = hcq2A; hcq2A = hcq2B; hcq2B = bt;
        t = hcsA; hcsA = hcsB; hcsB = t;
    }

    // ---- leaf step (M = 32768) ----
    {
        int M = MAXM;
        int gy = M / 128;
        igemm<0><<<dim3(768/128, gy), 512, IG_DYNSMEM>>>(
            xcq1, xcq2, xcs, wihq1, wihq2, wihs, b_ih, gi, M, 768, HH, nullptr);
        igemm<0><<<dim3(768/128, gy), 512, IG_DYNSMEM>>>(
            hcq1A, hcq2A, hcsA, whhq1, whhq2, whhs, b_hh, gh, M, 768, RR, nullptr);
        gru_quant_kernel<<<cdiv(M, 8), 256>>>(gi, gh, hcA, hcq1A, hcq2A, hcsA, M);
        hb_kernel<<<cdiv(M*32, 256), 256>>>(xcA, hcA, W_hb, b_hb, dA, dA, M);
        out_kernel<<<cdiv(M*(HH+1), 256), 256>>>(xcA, dA, (float*)d_out);
    }
}

// round 9
// speedup vs baseline: 2.4174x; 2.4174x over previous
#include <cuda_runtime.h>
#include <cuda_bf16.h>
#include <cuda_fp16.h>
#include <math.h>
#include <stdint.h>

// ---------------------------------------------------------------------------
// Problem constants
// ---------------------------------------------------------------------------
#define BB   64
#define SS   32
#define HH   1024
#define RR   256
#define DEPTH 9
#define MAXM (BB*512)

#define SELU_SCALE 1.0507009873554805f
#define SELU_ALPHA 1.6732632423543772f

typedef __nv_bfloat16 bf16;

__device__ __forceinline__ float seluf(float v) {
    return v > 0.f ? SELU_SCALE * v : SELU_SCALE * SELU_ALPHA * expm1f(v);
}
__device__ __forceinline__ float sigmoidf_(float v) {
    return 1.f / (1.f + __expf(-v));
}
__device__ __forceinline__ void split1(float v, bf16& h, bf16& l) {
    h = __float2bfloat16(v);
    l = __float2bfloat16(v - __bfloat162float(h));
}

// ---------------------------------------------------------------------------
// Scratch (device globals; allocation is forbidden)
// ---------------------------------------------------------------------------
__device__ float g_xcA[(size_t)MAXM * HH];
__device__ float g_xcB[(size_t)MAXM * HH];
__device__ float g_hcA[(size_t)MAXM * RR];
__device__ float g_hcB[(size_t)MAXM * RR];
__device__ float g_dA[MAXM];
__device__ float g_dB[MAXM];
__device__ float g_gi[(size_t)MAXM * 3 * RR];
__device__ float g_gh[(size_t)MAXM * 3 * RR];
__device__ float g_y [(size_t)BB * SS * HH];
__device__ __half g_xcf16[(size_t)MAXM * HH];
__device__ __half g_hf16A[(size_t)MAXM * RR];
__device__ __half g_hf16B[(size_t)MAXM * RR];
__device__ bf16 g_sxh[(size_t)BB * SS * HH];
__device__ bf16 g_sxl[(size_t)BB * SS * HH];
__device__ bf16 g_xhh[(size_t)MAXM * (HH + RR)];
__device__ bf16 g_xhl[(size_t)MAXM * (HH + RR)];
__device__ bf16 g_lrh[(size_t)(MAXM/2) * 2 * HH];
__device__ bf16 g_lrl[(size_t)(MAXM/2) * 2 * HH];
// weights
__device__ bf16 g_Whidh[HH * HH];
__device__ bf16 g_Whidl[HH * HH];
__device__ bf16 g_Wbrh[2 * HH * (HH + RR)];
__device__ bf16 g_Wbrl[2 * HH * (HH + RR)];
__device__ __half g_Wihf[3 * RR * HH];
__device__ __half g_Whhf[3 * RR * RR];

// ---------------------------------------------------------------------------
// mma.sync helpers
// ---------------------------------------------------------------------------
__device__ __forceinline__ void ldsm4(uint32_t* r, const void* p) {
    uint32_t a = (uint32_t)__cvta_generic_to_shared(p);
    asm volatile("ldmatrix.sync.aligned.m8n8.x4.shared.b16 {%0,%1,%2,%3}, [%4];"
        : "=r"(r[0]), "=r"(r[1]), "=r"(r[2]), "=r"(r[3]) : "r"(a));
}
__device__ __forceinline__ void mma_bf16(float* d, const uint32_t* a, uint32_t b0, uint32_t b1) {
    asm volatile("mma.sync.aligned.m16n8k16.row.col.f32.bf16.bf16.f32 "
        "{%0,%1,%2,%3}, {%4,%5,%6,%7}, {%8,%9}, {%0,%1,%2,%3};"
        : "+f"(d[0]), "+f"(d[1]), "+f"(d[2]), "+f"(d[3])
        : "r"(a[0]), "r"(a[1]), "r"(a[2]), "r"(a[3]), "r"(b0), "r"(b1));
}
__device__ __forceinline__ void mma_f16(float* d, const uint32_t* a, uint32_t b0, uint32_t b1) {
    asm volatile("mma.sync.aligned.m16n8k16.row.col.f32.f16.f16.f32 "
        "{%0,%1,%2,%3}, {%4,%5,%6,%7}, {%8,%9}, {%0,%1,%2,%3};"
        : "+f"(d[0]), "+f"(d[1]), "+f"(d[2]), "+f"(d[3])
        : "r"(a[0]), "r"(a[1]), "r"(a[2]), "r"(a[3]), "r"(b0), "r"(b1));
}

// ---------------------------------------------------------------------------
// 3-term bf16 split GEMM (the proven R3 kernel, + fp16 output option):
//   C[M,N] = epi( Ah@Wh^T + Al@Wh^T + Ah@Wl^T + bias )
//   EPI 0: bias   EPI 1: selu   EPI 2: P[r>>1] - selu
// ---------------------------------------------------------------------------
template<int EPI, bool OF32, bool OBF, bool OF16>
__global__ __launch_bounds__(256, 2)
void hgemm3(const bf16* __restrict__ Ah, const bf16* __restrict__ Al,
            const bf16* __restrict__ Wh, const bf16* __restrict__ Wl,
            const float* __restrict__ bias,
            float* __restrict__ Cf, bf16* __restrict__ Chi, bf16* __restrict__ Clo,
            __half* __restrict__ Cf16,
            int M, int N, int K, const float* __restrict__ P)
{
    __shared__ bf16 As[2][128][40];
    __shared__ bf16 Ws[2][128][40];

    const int tid = threadIdx.x;
    const int warp = tid >> 5, lane = tid & 31;
    const int wm = warp >> 2, wn = warp & 3;      // 2 x 4 warp grid
    const int row0 = blockIdx.y * 128, col0 = blockIdx.x * 128;

    const int kt = K >> 5;
    const int total = 3 * kt;

    float acc[4][4][4];
    #pragma unroll
    for (int a = 0; a < 4; a++)
        #pragma unroll
        for (int b = 0; b < 4; b++)
            #pragma unroll
            for (int c = 0; c < 4; c++) acc[a][b][c] = 0.f;

    uint4 ra[2], rw[2];

    auto loadg = [&](int it) {
        int ph = (it >= 2 * kt) ? 2 : (it >= kt ? 1 : 0);
        int k0 = (it - ph * kt) << 5;
        const bf16* Ap = (ph == 1) ? Al : Ah;
        const bf16* Wp = (ph == 2) ? Wl : Wh;
        #pragma unroll
        for (int i = 0; i < 2; i++) {
            int u = (i << 8) + tid;
            int r = u >> 2, c = (u & 3) << 3;
            int gr = row0 + r;
            ra[i] = (gr < M) ? *(const uint4*)(Ap + (size_t)gr * K + k0 + c)
                             : make_uint4(0u, 0u, 0u, 0u);
            rw[i] = *(const uint4*)(Wp + (size_t)(col0 + r) * K + k0 + c);
        }
    };
    auto sts = [&](int buf) {
        #pragma unroll
        for (int i = 0; i < 2; i++) {
            int u = (i << 8) + tid;
            int r = u >> 2, c = (u & 3) << 3;
            *(uint4*)&As[buf][r][c] = ra[i];
            *(uint4*)&Ws[buf][r][c] = rw[i];
        }
    };

    loadg(0);
    sts(0);
    __syncthreads();

    const int a_r = (lane & 15);
    const int a_c = (lane >> 4) << 3;
    const int b_r = (lane & 7) + ((lane >> 4) << 3);
    const int b_c = ((lane >> 3) & 1) << 3;

    for (int it = 0; it < total; ++it) {
        int cur = it & 1;
        bool more = (it + 1 < total);
        if (more) loadg(it + 1);

        #pragma unroll
        for (int s = 0; s < 2; s++) {
            uint32_t afr[4][4], bfr[2][4];
            #pragma unroll
            for (int mt = 0; mt < 4; mt++)
                ldsm4(afr[mt], &As[cur][wm * 64 + mt * 16 + a_r][s * 16 + a_c]);
            #pragma unroll
            for (int p = 0; p < 2; p++)
                ldsm4(bfr[p], &Ws[cur][wn * 32 + p * 16 + b_r][s * 16 + b_c]);
            #pragma unroll
            for (int mt = 0; mt < 4; mt++)
                #pragma unroll
                for (int nt = 0; nt < 4; nt++)
                    mma_bf16(acc[mt][nt], afr[mt],
                             bfr[nt >> 1][(nt & 1) * 2], bfr[nt >> 1][(nt & 1) * 2 + 1]);
        }

        if (more) sts(cur ^ 1);
        __syncthreads();
    }

    // ---- epilogue ----
    const int g = lane >> 2, t = lane & 3;
    #pragma unroll
    for (int mt = 0; mt < 4; mt++) {
        #pragma unroll
        for (int half = 0; half < 2; half++) {
            int r = row0 + wm * 64 + mt * 16 + g + half * 8;
            if (r >= M) continue;
            #pragma unroll
            for (int nt = 0; nt < 4; nt++) {
                int c = col0 + wn * 32 + nt * 8 + (t << 1);
                float v0 = acc[mt][nt][half * 2 + 0] + bias[c];
                float v1 = acc[mt][nt][half * 2 + 1] + bias[c + 1];
                if (EPI == 1) { v0 = seluf(v0); v1 = seluf(v1); }
                if (EPI == 2) {
                    float2 p = *(const float2*)(P + (size_t)(r >> 1) * HH + c);
                    v0 = p.x - seluf(v0);
                    v1 = p.y - seluf(v1);
                }
                if (OF32) *(float2*)(Cf + (size_t)r * N + c) = make_float2(v0, v1);
                if (OBF) {
                    bf16 h0, l0, h1, l1;
                    split1(v0, h0, l0); split1(v1, h1, l1);
                    *(__nv_bfloat162*)(Chi + (size_t)r * N + c) = __nv_bfloat162(h0, h1);
                    *(__nv_bfloat162*)(Clo + (size_t)r * N + c) = __nv_bfloat162(l0, l1);
                }
                if (OF16)
                    *(__half2*)(Cf16 + (size_t)r * N + c) =
                        __floats2half2_rn(v0, v1);
            }
        }
    }
}

// ---------------------------------------------------------------------------
// 1-term fp16 GEMM (GRU gates): C = A[rowmap]@W^T + bias   (fp32 out)
// rowmap: source A row = (tile row) >> ashift   (parent repeat folded in)
// ---------------------------------------------------------------------------
__global__ __launch_bounds__(256, 2)
void hgemm1(const __half* __restrict__ A, const __half* __restrict__ W,
            const float* __restrict__ bias, float* __restrict__ Cf,
            int M, int N, int K, int ashift)
{
    __shared__ __half As[2][128][40];
    __shared__ __half Ws[2][128][40];

    const int tid = threadIdx.x;
    const int warp = tid >> 5, lane = tid & 31;
    const int wm = warp >> 2, wn = warp & 3;
    const int row0 = blockIdx.y * 128, col0 = blockIdx.x * 128;

    const int total = K >> 5;

    float acc[4][4][4];
    #pragma unroll
    for (int a = 0; a < 4; a++)
        #pragma unroll
        for (int b = 0; b < 4; b++)
            #pragma unroll
            for (int c = 0; c < 4; c++) acc[a][b][c] = 0.f;

    uint4 ra[2], rw[2];

    auto loadg = [&](int it) {
        int k0 = it << 5;
        #pragma unroll
        for (int i = 0; i < 2; i++) {
            int u = (i << 8) + tid;
            int r = u >> 2, c = (u & 3) << 3;
            int gr = row0 + r;
            ra[i] = (gr < M) ? *(const uint4*)(A + (size_t)(gr >> ashift) * K + k0 + c)
                             : make_uint4(0u, 0u, 0u, 0u);
            rw[i] = *(const uint4*)(W + (size_t)(col0 + r) * K + k0 + c);
        }
    };
    auto sts = [&](int buf) {
        #pragma unroll
        for (int i = 0; i < 2; i++) {
            int u = (i << 8) + tid;
            int r = u >> 2, c = (u & 3) << 3;
            *(uint4*)&As[buf][r][c] = ra[i];
            *(uint4*)&Ws[buf][r][c] = rw[i];
        }
    };

    loadg(0);
    sts(0);
    __syncthreads();

    const int a_r = (lane & 15);
    const int a_c = (lane >> 4) << 3;
    const int b_r = (lane & 7) + ((lane >> 4) << 3);
    const int b_c = ((lane >> 3) & 1) << 3;

    for (int it = 0; it < total; ++it) {
        int cur = it & 1;
        bool more = (it + 1 < total);
        if (more) loadg(it + 1);

        #pragma unroll
        for (int s = 0; s < 2; s++) {
            uint32_t afr[4][4], bfr[2][4];
            #pragma unroll
            for (int mt = 0; mt < 4; mt++)
                ldsm4(afr[mt], &As[cur][wm * 64 + mt * 16 + a_r][s * 16 + a_c]);
            #pragma unroll
            for (int p = 0; p < 2; p++)
                ldsm4(bfr[p], &Ws[cur][wn * 32 + p * 16 + b_r][s * 16 + b_c]);
            #pragma unroll
            for (int mt = 0; mt < 4; mt++)
                #pragma unroll
                for (int nt = 0; nt < 4; nt++)
                    mma_f16(acc[mt][nt], afr[mt],
                            bfr[nt >> 1][(nt & 1) * 2], bfr[nt >> 1][(nt & 1) * 2 + 1]);
        }

        if (more) sts(cur ^ 1);
        __syncthreads();
    }

    const int g = lane >> 2, t = lane & 3;
    #pragma unroll
    for (int mt = 0; mt < 4; mt++) {
        #pragma unroll
        for (int half = 0; half < 2; half++) {
            int r = row0 + wm * 64 + mt * 16 + g + half * 8;
            if (r >= M) continue;
            #pragma unroll
            for (int nt = 0; nt < 4; nt++) {
                int c = col0 + wn * 32 + nt * 8 + (t << 1);
                float v0 = acc[mt][nt][half * 2 + 0] + bias[c];
                float v1 = acc[mt][nt][half * 2 + 1] + bias[c + 1];
                *(float2*)(Cf + (size_t)r * N + c) = make_float2(v0, v1);
            }
        }
    }
}

// ---------------------------------------------------------------------------
// Fused GRU + hb + depth + xh-split. Warp per row, 8 warps/block.
//   h_old = hcPrev[m >> shift]; hc_new = GRU(gi[m], gh[m], h_old)
//   dOut[m] = dPrev[m >> shift] + sigmoid([xc|hc_new].Whb + bhb)
//   WRITE_XH: xhh/xhl = bf16 hi/lo of [xc[m] | hc_new]
//   WRITE_HC: hcOut fp32 + hf16Out
// ---------------------------------------------------------------------------
template<bool WRITE_XH, bool WRITE_HC>
__global__ void gru_fused(const float* __restrict__ gi, const float* __restrict__ gh,
                          const float* __restrict__ hcPrev, const float* __restrict__ xc,
                          const float* __restrict__ Whb, const float* __restrict__ bhb,
                          const float* __restrict__ dPrev, float* __restrict__ dOut,
                          float* __restrict__ hcOut, __half* __restrict__ hf16Out,
                          bf16* __restrict__ xhh, bf16* __restrict__ xhl,
                          int M, int shift)
{
    const int m = blockIdx.x * 8 + (threadIdx.x >> 5);
    const int lane = threadIdx.x & 31;
    if (m >= M) return;
    const int p = m >> shift;
    const size_t o = (size_t)m * 768;
    const size_t hp = (size_t)p * RR;
    const size_t hm = (size_t)m * RR;

    float v[8];
    #pragma unroll
    for (int u = 0; u < 8; u++) {
        int j = lane + 32 * u;
        float ir = gi[o + j], iz = gi[o + 256 + j], inn = gi[o + 512 + j];
        float hr = gh[o + j], hz = gh[o + 256 + j], hn  = gh[o + 512 + j];
        float r = sigmoidf_(ir + hr);
        float z = sigmoidf_(iz + hz);
        float n = tanhf(inn + r * hn);
        float h = hcPrev[hp + j];
        float nv = (1.f - z) * n + z * h;
        v[u] = nv;
        if (WRITE_HC) {
            hcOut[hm + j] = nv;
            hf16Out[hm + j] = __float2half(nv);
        }
    }

    // hb dot over [xc(1024) | hc_new(256)]
    const float4* xr = (const float4*)(xc + (size_t)m * HH);
    const float4* w4 = (const float4*)Whb;
    float s = 0.f;
    #pragma unroll
    for (int i8 = 0; i8 < 8; i8++) {
        int i = lane + 32 * i8;
        float4 a = xr[i], b = w4[i];
        s += a.x * b.x + a.y * b.y + a.z * b.z + a.w * b.w;
        if (WRITE_XH) {
            bf16 h0, l0, h1, l1, h2, l2, h3, l3;
            split1(a.x, h0, l0); split1(a.y, h1, l1);
            split1(a.z, h2, l2); split1(a.w, h3, l3);
            size_t off = (size_t)m * (HH + RR) + i * 4;
            *(__nv_bfloat162*)(xhh + off)     = __nv_bfloat162(h0, h1);
            *(__nv_bfloat162*)(xhh + off + 2) = __nv_bfloat162(h2, h3);
            *(__nv_bfloat162*)(xhl + off)     = __nv_bfloat162(l0, l1);
            *(__nv_bfloat162*)(xhl + off + 2) = __nv_bfloat162(l2, l3);
        }
    }
    #pragma unroll
    for (int u = 0; u < 8; u++) {
        int j = lane + 32 * u;
        s += v[u] * Whb[1024 + j];
        if (WRITE_XH) {
            bf16 h0, l0;
            split1(v[u], h0, l0);
            size_t off = (size_t)m * (HH + RR) + 1024 + j;
            xhh[off] = h0;
            xhl[off] = l0;
        }
    }
    #pragma unroll
    for (int off = 16; off; off >>= 1) s += __shfl_xor_sync(0xffffffffu, s, off);
    if (lane == 0) dOut[m] = dPrev[p] + sigmoidf_(s + bhb[0]);
}

// ---------------------------------------------------------------------------
// Misc elementwise kernels
// ---------------------------------------------------------------------------
__global__ void split_kernel(const float* __restrict__ in, bf16* __restrict__ h,
                             bf16* __restrict__ l, int n) {
    int i = blockIdx.x * blockDim.x + threadIdx.x;
    if (i < n) split1(in[i], h[i], l[i]);
}
__global__ void selu_split_kernel(const float* __restrict__ in, bf16* __restrict__ h,
                                  bf16* __restrict__ l, int n) {
    int i = blockIdx.x * blockDim.x + threadIdx.x;
    if (i < n) split1(seluf(in[i]), h[i], l[i]);
}
__global__ void half_cast_kernel(const float* __restrict__ in, __half* __restrict__ out, int n) {
    int i = blockIdx.x * blockDim.x + threadIdx.x;
    if (i < n) out[i] = __float2half(in[i]);
}
__global__ void mean_kernel(const float* __restrict__ y, float* __restrict__ xc,
                            __half* __restrict__ xf16) {
    int i = blockIdx.x * blockDim.x + threadIdx.x;   // over B*H
    if (i >= BB * HH) return;
    int b = i >> 10, h = i & (HH - 1);
    float s = 0.f;
    #pragma unroll 8
    for (int t = 0; t < SS; t++) s += y[((size_t)(b * SS + t)) * HH + h];
    float v = s * (1.f / SS);
    xc[i] = v;
    xf16[i] = __float2half(v);
}
__global__ void zero32_kernel(uint32_t* p, int n) {
    int i = blockIdx.x * blockDim.x + threadIdx.x;
    if (i < n) p[i] = 0u;
}
__global__ void out_kernel(const float* __restrict__ xc, const float* __restrict__ dep,
                           float* __restrict__ out) {
    int i = blockIdx.x * blockDim.x + threadIdx.x;
    if (i >= MAXM * (HH + 1)) return;
    int m = i / (HH + 1), k = i - m * (HH + 1);
    out[i] = (k < HH) ? xc[(size_t)m * HH + k] : dep[m];
}

// ---------------------------------------------------------------------------
// Host driver (graph-capturable: only kernel launches)
// ---------------------------------------------------------------------------
static inline int cdiv(int a, int b) { return (a + b - 1) / b; }

extern "C" void kernel_launch(void* const* d_in, const int* in_sizes, int n_in,
                              void* d_out, int out_size)
{
    const float* x        = (const float*)d_in[0];
    const float* W_hidden = (const float*)d_in[1];
    const float* b_hidden = (const float*)d_in[2];
    const float* W_hb     = (const float*)d_in[3];
    const float* b_hb     = (const float*)d_in[4];
    const float* W_branch = (const float*)d_in[5];
    const float* b_branch = (const float*)d_in[6];
    const float* W_ih     = (const float*)d_in[7];
    const float* W_hh     = (const float*)d_in[8];
    const float* b_ih     = (const float*)d_in[9];
    const float* b_hh     = (const float*)d_in[10];

    float *xcA, *xcB, *hcA, *hcB, *dA, *dB, *gi, *gh, *y;
    __half *xcf16, *hf16A, *hf16B, *Wihf, *Whhf;
    bf16 *sxh, *sxl, *xhh, *xhl, *lrh, *lrl, *Whidh, *Whidl, *Wbrh, *Wbrl;

    cudaGetSymbolAddress((void**)&xcA, g_xcA);   cudaGetSymbolAddress((void**)&xcB, g_xcB);
    cudaGetSymbolAddress((void**)&hcA, g_hcA);   cudaGetSymbolAddress((void**)&hcB, g_hcB);
    cudaGetSymbolAddress((void**)&dA,  g_dA);    cudaGetSymbolAddress((void**)&dB,  g_dB);
    cudaGetSymbolAddress((void**)&gi,  g_gi);    cudaGetSymbolAddress((void**)&gh,  g_gh);
    cudaGetSymbolAddress((void**)&y,   g_y);
    cudaGetSymbolAddress((void**)&xcf16, g_xcf16);
    cudaGetSymbolAddress((void**)&hf16A, g_hf16A); cudaGetSymbolAddress((void**)&hf16B, g_hf16B);
    cudaGetSymbolAddress((void**)&sxh, g_sxh);   cudaGetSymbolAddress((void**)&sxl, g_sxl);
    cudaGetSymbolAddress((void**)&xhh, g_xhh);   cudaGetSymbolAddress((void**)&xhl, g_xhl);
    cudaGetSymbolAddress((void**)&lrh, g_lrh);   cudaGetSymbolAddress((void**)&lrl, g_lrl);
    cudaGetSymbolAddress((void**)&Whidh, g_Whidh); cudaGetSymbolAddress((void**)&Whidl, g_Whidl);
    cudaGetSymbolAddress((void**)&Wbrh, g_Wbrh);   cudaGetSymbolAddress((void**)&Wbrl, g_Wbrl);
    cudaGetSymbolAddress((void**)&Wihf, g_Wihf);   cudaGetSymbolAddress((void**)&Whhf, g_Whhf);

    const int nsx = BB * SS * HH;

    // ---- weight prep ----
    split_kernel<<<cdiv(HH*HH, 256), 256>>>(W_hidden, Whidh, Whidl, HH*HH);
    split_kernel<<<cdiv(2*HH*(HH+RR), 256), 256>>>(W_branch, Wbrh, Wbrl, 2*HH*(HH+RR));
    half_cast_kernel<<<cdiv(3*RR*HH, 256), 256>>>(W_ih, Wihf, 3*RR*HH);
    half_cast_kernel<<<cdiv(3*RR*RR, 256), 256>>>(W_hh, Whhf, 3*RR*RR);

    // ---- root: xc0 = mean_s selu(selu(x) @ W_hidden^T + b_hidden) ----
    selu_split_kernel<<<cdiv(nsx, 256), 256>>>(x, sxh, sxl, nsx);
    hgemm3<1, true, false, false><<<dim3(HH/128, (BB*SS)/128), 256>>>(
        sxh, sxl, Whidh, Whidl, b_hidden, y, nullptr, nullptr, nullptr,
        BB*SS, HH, HH, nullptr);
    mean_kernel<<<cdiv(BB*HH, 256), 256>>>(y, xcA, xcf16);

    zero32_kernel<<<cdiv(BB*RR, 256), 256>>>((uint32_t*)hcA, BB*RR);
    zero32_kernel<<<cdiv(BB*RR/2, 256), 256>>>((uint32_t*)hf16A, BB*RR/2);
    zero32_kernel<<<1, 64>>>((uint32_t*)dA, BB);

    // ---- levels 0 .. DEPTH-1 ----
    for (int d = 0; d < DEPTH; d++) {
        int M  = BB << d;
        int M2 = M << 1;
        int gy = cdiv(M, 128);
        int shift = (d == 0) ? 0 : 1;

        hgemm1<<<dim3(6, gy), 256>>>(xcf16, Wihf, b_ih, gi, M, 768, HH, 0);
        hgemm1<<<dim3(6, gy), 256>>>(hf16A, Whhf, b_hh, gh, M, 768, RR, shift);

        gru_fused<true, true><<<cdiv(M, 8), 256>>>(
            gi, gh, hcA, xcA, W_hb, b_hb, dA, dB,
            hcB, hf16B, xhh, xhl, M, shift);

        hgemm3<1, false, true, false><<<dim3(16, gy), 256>>>(
            xhh, xhl, Wbrh, Wbrl, b_branch, nullptr, lrh, lrl, nullptr,
            M, 2*HH, HH+RR, nullptr);

        hgemm3<2, true, false, true><<<dim3(8, cdiv(M2, 128)), 256>>>(
            lrh, lrl, Whidh, Whidl, b_hidden, xcB, nullptr, nullptr, xcf16,
            M2, HH, HH, xcA);

        float* t; __half* ht;
        t = xcA; xcA = xcB; xcB = t;
        t = hcA; hcA = hcB; hcB = t;
        t = dA;  dA  = dB;  dB  = t;
        ht = hf16A; hf16A = hf16B; hf16B = ht;
    }

    // ---- leaf step (M = 32768): GRU + hb only (no xh, no hc writeback) ----
    {
        int M = MAXM;
        int gy = M / 128;
        hgemm1<<<dim3(6, gy), 256>>>(xcf16, Wihf, b_ih, gi, M, 768, HH, 0);
        hgemm1<<<dim3(6, gy), 256>>>(hf16A, Whhf, b_hh, gh, M, 768, RR, 1);
        gru_fused<false, false><<<cdiv(M, 8), 256>>>(
            gi, gh, hcA, xcA, W_hb, b_hb, dA, dB,
            nullptr, nullptr, nullptr, nullptr, M, 1);
        out_kernel<<<cdiv(M*(HH+1), 256), 256>>>(xcA, dB, (float*)d_out);
    }
}

// round 10
// speedup vs baseline: 3.1639x; 1.3088x over previous
#include <cuda_runtime.h>
#include <cuda_fp16.h>
#include <math.h>
#include <stdint.h>

// ---------------------------------------------------------------------------
// Problem constants
// ---------------------------------------------------------------------------
#define BB   64
#define SS   32
#define HH   1024
#define RR   256
#define DEPTH 9
#define MAXM (BB*512)

#define SELU_SCALE 1.0507009873554805f
#define SELU_ALPHA 1.6732632423543772f

__device__ __forceinline__ float seluf(float v) {
    return v > 0.f ? SELU_SCALE * v : SELU_SCALE * SELU_ALPHA * expm1f(v);
}
__device__ __forceinline__ float sigmoidf_(float v) {
    return 1.f / (1.f + __expf(-v));
}

// ---------------------------------------------------------------------------
// Scratch (device globals; allocation is forbidden)
// ---------------------------------------------------------------------------
__device__ float g_xcA[(size_t)MAXM * HH];
__device__ float g_xcB[(size_t)MAXM * HH];
__device__ float g_hcA[(size_t)MAXM * RR];
__device__ float g_hcB[(size_t)MAXM * RR];
__device__ float g_dA[MAXM];
__device__ float g_dB[MAXM];
__device__ float g_gi[(size_t)MAXM * 3 * RR];
__device__ float g_gh[(size_t)MAXM * 3 * RR];
__device__ float g_y [(size_t)BB * SS * HH];
__device__ __half g_xcf16[(size_t)MAXM * HH];
__device__ __half g_hf16A[(size_t)MAXM * RR];
__device__ __half g_hf16B[(size_t)MAXM * RR];
__device__ __half g_sxf[(size_t)BB * SS * HH];
__device__ __half g_xhf[(size_t)MAXM * (HH + RR)];
__device__ __half g_lrf[(size_t)MAXM * HH];      // branch out viewed [2M,1024]
// weights (fp16 hi/lo for the 2-term GEMMs; single fp16 for GRU)
__device__ __half g_Whidh[HH * HH];
__device__ __half g_Whidl[HH * HH];
__device__ __half g_Wbrh[2 * HH * (HH + RR)];
__device__ __half g_Wbrl[2 * HH * (HH + RR)];
__device__ __half g_Wihf[3 * RR * HH];
__device__ __half g_Whhf[3 * RR * RR];

// ---------------------------------------------------------------------------
// mma.sync helpers
// ---------------------------------------------------------------------------
__device__ __forceinline__ void ldsm4(uint32_t* r, const void* p) {
    uint32_t a = (uint32_t)__cvta_generic_to_shared(p);
    asm volatile("ldmatrix.sync.aligned.m8n8.x4.shared.b16 {%0,%1,%2,%3}, [%4];"
        : "=r"(r[0]), "=r"(r[1]), "=r"(r[2]), "=r"(r[3]) : "r"(a));
}
__device__ __forceinline__ void mma_f16(float* d, const uint32_t* a, uint32_t b0, uint32_t b1) {
    asm volatile("mma.sync.aligned.m16n8k16.row.col.f32.f16.f16.f32 "
        "{%0,%1,%2,%3}, {%4,%5,%6,%7}, {%8,%9}, {%0,%1,%2,%3};"
        : "+f"(d[0]), "+f"(d[1]), "+f"(d[2]), "+f"(d[3])
        : "r"(a[0]), "r"(a[1]), "r"(a[2]), "r"(a[3]), "r"(b0), "r"(b1));
}

// ---------------------------------------------------------------------------
// 2-term fp16 GEMM: C[M,N] = epi( A@(Wh+Wl)^T + bias )
//   A single fp16; W split hi/lo fp16 (lossless weights), 2-phase K loop.
//   EPI 0: bias   EPI 1: selu   EPI 2: P[r>>1] - selu
// 128x128 CTA tile, 8 warps of 64x32, double-buffered smem (R3 structure).
// ---------------------------------------------------------------------------
template<int EPI, bool OF32, bool OF16>
__global__ __launch_bounds__(256, 2)
void hgemm2(const __half* __restrict__ A,
            const __half* __restrict__ Wh, const __half* __restrict__ Wl,
            const float* __restrict__ bias,
            float* __restrict__ Cf, __half* __restrict__ Cf16,
            int M, int N, int K, const float* __restrict__ P)
{
    __shared__ __half As[2][128][40];
    __shared__ __half Ws[2][128][40];

    const int tid = threadIdx.x;
    const int warp = tid >> 5, lane = tid & 31;
    const int wm = warp >> 2, wn = warp & 3;      // 2 x 4 warp grid
    const int row0 = blockIdx.y * 128, col0 = blockIdx.x * 128;

    const int kt = K >> 5;
    const int total = 2 * kt;

    float acc[4][4][4];
    #pragma unroll
    for (int a = 0; a < 4; a++)
        #pragma unroll
        for (int b = 0; b < 4; b++)
            #pragma unroll
            for (int c = 0; c < 4; c++) acc[a][b][c] = 0.f;

    uint4 ra[2], rw[2];

    auto loadg = [&](int it) {
        int ph = (it >= kt) ? 1 : 0;
        int k0 = (it - ph * kt) << 5;
        const __half* Wp = ph ? Wl : Wh;
        #pragma unroll
        for (int i = 0; i < 2; i++) {
            int u = (i << 8) + tid;
            int r = u >> 2, c = (u & 3) << 3;
            int gr = row0 + r;
            ra[i] = (gr < M) ? *(const uint4*)(A + (size_t)gr * K + k0 + c)
                             : make_uint4(0u, 0u, 0u, 0u);
            rw[i] = *(const uint4*)(Wp + (size_t)(col0 + r) * K + k0 + c);
        }
    };
    auto sts = [&](int buf) {
        #pragma unroll
        for (int i = 0; i < 2; i++) {
            int u = (i << 8) + tid;
            int r = u >> 2, c = (u & 3) << 3;
            *(uint4*)&As[buf][r][c] = ra[i];
            *(uint4*)&Ws[buf][r][c] = rw[i];
        }
    };

    loadg(0);
    sts(0);
    __syncthreads();

    const int a_r = (lane & 15);
    const int a_c = (lane >> 4) << 3;
    const int b_r = (lane & 7) + ((lane >> 4) << 3);
    const int b_c = ((lane >> 3) & 1) << 3;

    for (int it = 0; it < total; ++it) {
        int cur = it & 1;
        bool more = (it + 1 < total);
        if (more) loadg(it + 1);

        #pragma unroll
        for (int s = 0; s < 2; s++) {
            uint32_t afr[4][4], bfr[2][4];
            #pragma unroll
            for (int mt = 0; mt < 4; mt++)
                ldsm4(afr[mt], &As[cur][wm * 64 + mt * 16 + a_r][s * 16 + a_c]);
            #pragma unroll
            for (int p = 0; p < 2; p++)
                ldsm4(bfr[p], &Ws[cur][wn * 32 + p * 16 + b_r][s * 16 + b_c]);
            #pragma unroll
            for (int mt = 0; mt < 4; mt++)
                #pragma unroll
                for (int nt = 0; nt < 4; nt++)
                    mma_f16(acc[mt][nt], afr[mt],
                            bfr[nt >> 1][(nt & 1) * 2], bfr[nt >> 1][(nt & 1) * 2 + 1]);
        }

        if (more) sts(cur ^ 1);
        __syncthreads();
    }

    // ---- epilogue ----
    const int g = lane >> 2, t = lane & 3;
    #pragma unroll
    for (int mt = 0; mt < 4; mt++) {
        #pragma unroll
        for (int half = 0; half < 2; half++) {
            int r = row0 + wm * 64 + mt * 16 + g + half * 8;
            if (r >= M) continue;
            #pragma unroll
            for (int nt = 0; nt < 4; nt++) {
                int c = col0 + wn * 32 + nt * 8 + (t << 1);
                float v0 = acc[mt][nt][half * 2 + 0] + bias[c];
                float v1 = acc[mt][nt][half * 2 + 1] + bias[c + 1];
                if (EPI == 1) { v0 = seluf(v0); v1 = seluf(v1); }
                if (EPI == 2) {
                    float2 p = *(const float2*)(P + (size_t)(r >> 1) * HH + c);
                    v0 = p.x - seluf(v0);
                    v1 = p.y - seluf(v1);
                }
                if (OF32) *(float2*)(Cf + (size_t)r * N + c) = make_float2(v0, v1);
                if (OF16)
                    *(__half2*)(Cf16 + (size_t)r * N + c) = __floats2half2_rn(v0, v1);
            }
        }
    }
}

// ---------------------------------------------------------------------------
// 1-term fp16 GEMM (GRU gates): C = A[rowmap]@W^T + bias   (fp32 out)
// rowmap: source A row = (tile row) >> ashift   (parent repeat folded in)
// ---------------------------------------------------------------------------
__global__ __launch_bounds__(256, 2)
void hgemm1(const __half* __restrict__ A, const __half* __restrict__ W,
            const float* __restrict__ bias, float* __restrict__ Cf,
            int M, int N, int K, int ashift)
{
    __shared__ __half As[2][128][40];
    __shared__ __half Ws[2][128][40];

    const int tid = threadIdx.x;
    const int warp = tid >> 5, lane = tid & 31;
    const int wm = warp >> 2, wn = warp & 3;
    const int row0 = blockIdx.y * 128, col0 = blockIdx.x * 128;

    const int total = K >> 5;

    float acc[4][4][4];
    #pragma unroll
    for (int a = 0; a < 4; a++)
        #pragma unroll
        for (int b = 0; b < 4; b++)
            #pragma unroll
            for (int c = 0; c < 4; c++) acc[a][b][c] = 0.f;

    uint4 ra[2], rw[2];

    auto loadg = [&](int it) {
        int k0 = it << 5;
        #pragma unroll
        for (int i = 0; i < 2; i++) {
            int u = (i << 8) + tid;
            int r = u >> 2, c = (u & 3) << 3;
            int gr = row0 + r;
            ra[i] = (gr < M) ? *(const uint4*)(A + (size_t)(gr >> ashift) * K + k0 + c)
                             : make_uint4(0u, 0u, 0u, 0u);
            rw[i] = *(const uint4*)(W + (size_t)(col0 + r) * K + k0 + c);
        }
    };
    auto sts = [&](int buf) {
        #pragma unroll
        for (int i = 0; i < 2; i++) {
            int u = (i << 8) + tid;
            int r = u >> 2, c = (u & 3) << 3;
            *(uint4*)&As[buf][r][c] = ra[i];
            *(uint4*)&Ws[buf][r][c] = rw[i];
        }
    };

    loadg(0);
    sts(0);
    __syncthreads();

    const int a_r = (lane & 15);
    const int a_c = (lane >> 4) << 3;
    const int b_r = (lane & 7) + ((lane >> 4) << 3);
    const int b_c = ((lane >> 3) & 1) << 3;

    for (int it = 0; it < total; ++it) {
        int cur = it & 1;
        bool more = (it + 1 < total);
        if (more) loadg(it + 1);

        #pragma unroll
        for (int s = 0; s < 2; s++) {
            uint32_t afr[4][4], bfr[2][4];
            #pragma unroll
            for (int mt = 0; mt < 4; mt++)
                ldsm4(afr[mt], &As[cur][wm * 64 + mt * 16 + a_r][s * 16 + a_c]);
            #pragma unroll
            for (int p = 0; p < 2; p++)
                ldsm4(bfr[p], &Ws[cur][wn * 32 + p * 16 + b_r][s * 16 + b_c]);
            #pragma unroll
            for (int mt = 0; mt < 4; mt++)
                #pragma unroll
                for (int nt = 0; nt < 4; nt++)
                    mma_f16(acc[mt][nt], afr[mt],
                            bfr[nt >> 1][(nt & 1) * 2], bfr[nt >> 1][(nt & 1) * 2 + 1]);
        }

        if (more) sts(cur ^ 1);
        __syncthreads();
    }

    const int g = lane >> 2, t = lane & 3;
    #pragma unroll
    for (int mt = 0; mt < 4; mt++) {
        #pragma unroll
        for (int half = 0; half < 2; half++) {
            int r = row0 + wm * 64 + mt * 16 + g + half * 8;
            if (r >= M) continue;
            #pragma unroll
            for (int nt = 0; nt < 4; nt++) {
                int c = col0 + wn * 32 + nt * 8 + (t << 1);
                float v0 = acc[mt][nt][half * 2 + 0] + bias[c];
                float v1 = acc[mt][nt][half * 2 + 1] + bias[c + 1];
                *(float2*)(Cf + (size_t)r * N + c) = make_float2(v0, v1);
            }
        }
    }
}

// ---------------------------------------------------------------------------
// Fused GRU + hb + depth + xh(fp16). Warp per row, 8 warps/block.
//   h_old = hcPrev[m >> shift]; hc_new = GRU(gi[m], gh[m], h_old)
//   dOut[m] = dPrev[m >> shift] + sigmoid([xc|hc_new].Whb + bhb)
// ---------------------------------------------------------------------------
template<bool WRITE_XH, bool WRITE_HC>
__global__ void gru_fused(const float* __restrict__ gi, const float* __restrict__ gh,
                          const float* __restrict__ hcPrev, const float* __restrict__ xc,
                          const float* __restrict__ Whb, const float* __restrict__ bhb,
                          const float* __restrict__ dPrev, float* __restrict__ dOut,
                          float* __restrict__ hcOut, __half* __restrict__ hf16Out,
                          __half* __restrict__ xhf,
                          int M, int shift)
{
    const int m = blockIdx.x * 8 + (threadIdx.x >> 5);
    const int lane = threadIdx.x & 31;
    if (m >= M) return;
    const int p = m >> shift;
    const size_t o = (size_t)m * 768;
    const size_t hp = (size_t)p * RR;
    const size_t hm = (size_t)m * RR;

    float v[8];
    #pragma unroll
    for (int u = 0; u < 8; u++) {
        int j = lane + 32 * u;
        float ir = gi[o + j], iz = gi[o + 256 + j], inn = gi[o + 512 + j];
        float hr = gh[o + j], hz = gh[o + 256 + j], hn  = gh[o + 512 + j];
        float r = sigmoidf_(ir + hr);
        float z = sigmoidf_(iz + hz);
        float n = tanhf(inn + r * hn);
        float h = hcPrev[hp + j];
        float nv = (1.f - z) * n + z * h;
        v[u] = nv;
        if (WRITE_HC) {
            hcOut[hm + j] = nv;
            hf16Out[hm + j] = __float2half(nv);
        }
    }

    // hb dot over [xc(1024) | hc_new(256)]; optional fp16 xh write
    const float4* xr = (const float4*)(xc + (size_t)m * HH);
    const float4* w4 = (const float4*)Whb;
    float s = 0.f;
    #pragma unroll
    for (int i8 = 0; i8 < 8; i8++) {
        int i = lane + 32 * i8;
        float4 a = xr[i], b = w4[i];
        s += a.x * b.x + a.y * b.y + a.z * b.z + a.w * b.w;
        if (WRITE_XH) {
            size_t off = (size_t)m * (HH + RR) + i * 4;
            *(__half2*)(xhf + off)     = __floats2half2_rn(a.x, a.y);
            *(__half2*)(xhf + off + 2) = __floats2half2_rn(a.z, a.w);
        }
    }
    #pragma unroll
    for (int u = 0; u < 8; u++) {
        int j = lane + 32 * u;
        s += v[u] * Whb[1024 + j];
        if (WRITE_XH)
            xhf[(size_t)m * (HH + RR) + 1024 + j] = __float2half(v[u]);
    }
    #pragma unroll
    for (int off = 16; off; off >>= 1) s += __shfl_xor_sync(0xffffffffu, s, off);
    if (lane == 0) dOut[m] = dPrev[p] + sigmoidf_(s + bhb[0]);
}

// ---------------------------------------------------------------------------
// Misc elementwise kernels
// ---------------------------------------------------------------------------
__global__ void half_split_kernel(const float* __restrict__ in, __half* __restrict__ h,
                                  __half* __restrict__ l, int n) {
    int i = blockIdx.x * blockDim.x + threadIdx.x;
    if (i < n) {
        __half hv = __float2half(in[i]);
        h[i] = hv;
        l[i] = __float2half(in[i] - __half2float(hv));
    }
}
__global__ void half_cast_kernel(const float* __restrict__ in, __half* __restrict__ out, int n) {
    int i = blockIdx.x * blockDim.x + threadIdx.x;
    if (i < n) out[i] = __float2half(in[i]);
}
__global__ void selu_half_kernel(const float* __restrict__ in, __half* __restrict__ out, int n) {
    int i = blockIdx.x * blockDim.x + threadIdx.x;
    if (i < n) out[i] = __float2half(seluf(in[i]));
}
__global__ void mean_kernel(const float* __restrict__ y, float* __restrict__ xc,
                            __half* __restrict__ xf16) {
    int i = blockIdx.x * blockDim.x + threadIdx.x;   // over B*H
    if (i >= BB * HH) return;
    int b = i >> 10, h = i & (HH - 1);
    float s = 0.f;
    #pragma unroll 8
    for (int t = 0; t < SS; t++) s += y[((size_t)(b * SS + t)) * HH + h];
    float v = s * (1.f / SS);
    xc[i] = v;
    xf16[i] = __float2half(v);
}
__global__ void zero32_kernel(uint32_t* p, int n) {
    int i = blockIdx.x * blockDim.x + threadIdx.x;
    if (i < n) p[i] = 0u;
}
__global__ void out_kernel(const float* __restrict__ xc, const float* __restrict__ dep,
                           float* __restrict__ out) {
    int i = blockIdx.x * blockDim.x + threadIdx.x;
    if (i >= MAXM * (HH + 1)) return;
    int m = i / (HH + 1), k = i - m * (HH + 1);
    out[i] = (k < HH) ? xc[(size_t)m * HH + k] : dep[m];
}

// ---------------------------------------------------------------------------
// Host driver (graph-capturable: only kernel launches)
// ---------------------------------------------------------------------------
static inline int cdiv(int a, int b) { return (a + b - 1) / b; }

extern "C" void kernel_launch(void* const* d_in, const int* in_sizes, int n_in,
                              void* d_out, int out_size)
{
    const float* x        = (const float*)d_in[0];
    const float* W_hidden = (const float*)d_in[1];
    const float* b_hidden = (const float*)d_in[2];
    const float* W_hb     = (const float*)d_in[3];
    const float* b_hb     = (const float*)d_in[4];
    const float* W_branch = (const float*)d_in[5];
    const float* b_branch = (const float*)d_in[6];
    const float* W_ih     = (const float*)d_in[7];
    const float* W_hh     = (const float*)d_in[8];
    const float* b_ih     = (const float*)d_in[9];
    const float* b_hh     = (const float*)d_in[10];

    float *xcA, *xcB, *hcA, *hcB, *dA, *dB, *gi, *gh, *y;
    __half *xcf16, *hf16A, *hf16B, *sxf, *xhf, *lrf;
    __half *Whidh, *Whidl, *Wbrh, *Wbrl, *Wihf, *Whhf;

    cudaGetSymbolAddress((void**)&xcA, g_xcA);   cudaGetSymbolAddress((void**)&xcB, g_xcB);
    cudaGetSymbolAddress((void**)&hcA, g_hcA);   cudaGetSymbolAddress((void**)&hcB, g_hcB);
    cudaGetSymbolAddress((void**)&dA,  g_dA);    cudaGetSymbolAddress((void**)&dB,  g_dB);
    cudaGetSymbolAddress((void**)&gi,  g_gi);    cudaGetSymbolAddress((void**)&gh,  g_gh);
    cudaGetSymbolAddress((void**)&y,   g_y);
    cudaGetSymbolAddress((void**)&xcf16, g_xcf16);
    cudaGetSymbolAddress((void**)&hf16A, g_hf16A); cudaGetSymbolAddress((void**)&hf16B, g_hf16B);
    cudaGetSymbolAddress((void**)&sxf, g_sxf);
    cudaGetSymbolAddress((void**)&xhf, g_xhf);
    cudaGetSymbolAddress((void**)&lrf, g_lrf);
    cudaGetSymbolAddress((void**)&Whidh, g_Whidh); cudaGetSymbolAddress((void**)&Whidl, g_Whidl);
    cudaGetSymbolAddress((void**)&Wbrh, g_Wbrh);   cudaGetSymbolAddress((void**)&Wbrl, g_Wbrl);
    cudaGetSymbolAddress((void**)&Wihf, g_Wihf);   cudaGetSymbolAddress((void**)&Whhf, g_Whhf);

    const int nsx = BB * SS * HH;

    // ---- weight prep ----
    half_split_kernel<<<cdiv(HH*HH, 256), 256>>>(W_hidden, Whidh, Whidl, HH*HH);
    half_split_kernel<<<cdiv(2*HH*(HH+RR), 256), 256>>>(W_branch, Wbrh, Wbrl, 2*HH*(HH+RR));
    half_cast_kernel<<<cdiv(3*RR*HH, 256), 256>>>(W_ih, Wihf, 3*RR*HH);
    half_cast_kernel<<<cdiv(3*RR*RR, 256), 256>>>(W_hh, Whhf, 3*RR*RR);

    // ---- root: xc0 = mean_s selu(selu(x) @ W_hidden^T + b_hidden) ----
    selu_half_kernel<<<cdiv(nsx, 256), 256>>>(x, sxf, nsx);
    hgemm2<1, true, false><<<dim3(HH/128, (BB*SS)/128), 256>>>(
        sxf, Whidh, Whidl, b_hidden, y, nullptr, BB*SS, HH, HH, nullptr);
    mean_kernel<<<cdiv(BB*HH, 256), 256>>>(y, xcA, xcf16);

    zero32_kernel<<<cdiv(BB*RR, 256), 256>>>((uint32_t*)hcA, BB*RR);
    zero32_kernel<<<cdiv(BB*RR/2, 256), 256>>>((uint32_t*)hf16A, BB*RR/2);
    zero32_kernel<<<1, 64>>>((uint32_t*)dA, BB);

    // ---- levels 0 .. DEPTH-1 ----
    for (int d = 0; d < DEPTH; d++) {
        int M  = BB << d;
        int M2 = M << 1;
        int gy = cdiv(M, 128);
        int shift = (d == 0) ? 0 : 1;

        hgemm1<<<dim3(6, gy), 256>>>(xcf16, Wihf, b_ih, gi, M, 768, HH, 0);
        hgemm1<<<dim3(6, gy), 256>>>(hf16A, Whhf, b_hh, gh, M, 768, RR, shift);

        gru_fused<true, true><<<cdiv(M, 8), 256>>>(
            gi, gh, hcA, xcA, W_hb, b_hb, dA, dB,
            hcB, hf16B, xhf, M, shift);

        hgemm2<1, false, true><<<dim3(16, gy), 256>>>(
            xhf, Wbrh, Wbrl, b_branch, nullptr, lrf, M, 2*HH, HH+RR, nullptr);

        hgemm2<2, true, true><<<dim3(8, cdiv(M2, 128)), 256>>>(
            lrf, Whidh, Whidl, b_hidden, xcB, xcf16, M2, HH, HH, xcA);

        float* t; __half* ht;
        t = xcA; xcA = xcB; xcB = t;
        t = hcA; hcA = hcB; hcB = t;
        t = dA;  dA  = dB;  dB  = t;
        ht = hf16A; hf16A = hf16B; hf16B = ht;
    }

    // ---- leaf step (M = 32768): GRU + hb only ----
    {
        int M = MAXM;
        int gy = M / 128;
        hgemm1<<<dim3(6, gy), 256>>>(xcf16, Wihf, b_ih, gi, M, 768, HH, 0);
        hgemm1<<<dim3(6, gy), 256>>>(hf16A, Whhf, b_hh, gh, M, 768, RR, 1);
        gru_fused<false, false><<<cdiv(M, 8), 256>>>(
            gi, gh, hcA, xcA, W_hb, b_hb, dA, dB,
            nullptr, nullptr, nullptr, M, 1);
        out_kernel<<<cdiv(M*(HH+1), 256), 256>>>(xcA, dB, (float*)d_out);
    }
}

// round 12
// speedup vs baseline: 3.5587x; 1.1248x over previous
#include <cuda_runtime.h>
#include <cuda_fp16.h>
#include <math.h>
#include <stdint.h>

// ---------------------------------------------------------------------------
// Problem constants
// ---------------------------------------------------------------------------
#define BB   64
#define SS   32
#define HH   1024
#define RR   256
#define DEPTH 9
#define MAXM (BB*512)

#define SELU_SCALE 1.0507009873554805f
#define SELU_ALPHA 1.6732632423543772f

__device__ __forceinline__ float seluf(float v) {
    return v > 0.f ? SELU_SCALE * v : SELU_SCALE * SELU_ALPHA * expm1f(v);
}
__device__ __forceinline__ float sigmoidf_(float v) {
    return 1.f / (1.f + __expf(-v));
}

// ---------------------------------------------------------------------------
// Scratch (device globals; allocation is forbidden)
// ---------------------------------------------------------------------------
__device__ float g_xcA[(size_t)MAXM * HH];
__device__ float g_xcB[(size_t)MAXM * HH];
__device__ float g_hcA[(size_t)MAXM * RR];
__device__ float g_hcB[(size_t)MAXM * RR];
__device__ float g_dA[MAXM];
__device__ float g_dB[MAXM];
__device__ float g_gi[(size_t)MAXM * 3 * RR];
__device__ float g_gh[(size_t)MAXM * 3 * RR];
__device__ float g_y [(size_t)BB * SS * HH];
__device__ float g_ws[(size_t)8388608];          // split-K workspace (32 MB)
__device__ __half g_xcf16[(size_t)MAXM * HH];
__device__ __half g_hf16A[(size_t)MAXM * RR];
__device__ __half g_hf16B[(size_t)MAXM * RR];
__device__ __half g_sxf[(size_t)BB * SS * HH];
__device__ __half g_xhf[(size_t)MAXM * (HH + RR)];
__device__ __half g_lrf[(size_t)MAXM * HH];      // branch out viewed [2M,1024]
// weights (fp16 hi/lo for the 2-term GEMMs; single fp16 for GRU)
__device__ __half g_Whidh[HH * HH];
__device__ __half g_Whidl[HH * HH];
__device__ __half g_Wbrh[2 * HH * (HH + RR)];
__device__ __half g_Wbrl[2 * HH * (HH + RR)];
__device__ __half g_Wihf[3 * RR * HH];
__device__ __half g_Whhf[3 * RR * RR];

// ---------------------------------------------------------------------------
// mma.sync helpers
// ---------------------------------------------------------------------------
__device__ __forceinline__ void ldsm4(uint32_t* r, const void* p) {
    uint32_t a = (uint32_t)__cvta_generic_to_shared(p);
    asm volatile("ldmatrix.sync.aligned.m8n8.x4.shared.b16 {%0,%1,%2,%3}, [%4];"
        : "=r"(r[0]), "=r"(r[1]), "=r"(r[2]), "=r"(r[3]) : "r"(a));
}
__device__ __forceinline__ void mma_f16(float* d, const uint32_t* a, uint32_t b0, uint32_t b1) {
    asm volatile("mma.sync.aligned.m16n8k16.row.col.f32.f16.f16.f32 "
        "{%0,%1,%2,%3}, {%4,%5,%6,%7}, {%8,%9}, {%0,%1,%2,%3};"
        : "+f"(d[0]), "+f"(d[1]), "+f"(d[2]), "+f"(d[3])
        : "r"(a[0]), "r"(a[1]), "r"(a[2]), "r"(a[3]), "r"(b0), "r"(b1));
}

// ---------------------------------------------------------------------------
// 2-term fp16 GEMM: C[M,N] = epi( A@Wh^T + A[:, :K2]@Wl[:, :K2]^T + bias )
//   Phase 1: K (hi weights); phase 2: K2 (lo weights, may exclude trailing
//   columns -- used to skip the hc part of W_branch's lo term).
//   EPI 0: bias   EPI 1: selu   EPI 2: P[r>>1] - selu
// 128x128 CTA tile, 8 warps of 64x32, double-buffered smem.
// ---------------------------------------------------------------------------
template<int EPI, bool OF32, bool OF16>
__global__ __launch_bounds__(256, 2)
void hgemm2(const __half* __restrict__ A,
            const __half* __restrict__ Wh, const __half* __restrict__ Wl,
            const float* __restrict__ bias,
            float* __restrict__ Cf, __half* __restrict__ Cf16,
            int M, int N, int K, int K2, const float* __restrict__ P)
{
    __shared__ __half As[2][128][40];
    __shared__ __half Ws[2][128][40];

    const int tid = threadIdx.x;
    const int warp = tid >> 5, lane = tid & 31;
    const int wm = warp >> 2, wn = warp & 3;      // 2 x 4 warp grid
    const int row0 = blockIdx.y * 128, col0 = blockIdx.x * 128;

    const int kt1 = K >> 5;
    const int total = kt1 + (K2 >> 5);

    float acc[4][4][4];
    #pragma unroll
    for (int a = 0; a < 4; a++)
        #pragma unroll
        for (int b = 0; b < 4; b++)
            #pragma unroll
            for (int c = 0; c < 4; c++) acc[a][b][c] = 0.f;

    uint4 ra[2], rw[2];

    auto loadg = [&](int it) {
        int ph = (it >= kt1) ? 1 : 0;
        int k0 = (it - (ph ? kt1 : 0)) << 5;
        const __half* Wp = ph ? Wl : Wh;
        #pragma unroll
        for (int i = 0; i < 2; i++) {
            int u = (i << 8) + tid;
            int r = u >> 2, c = (u & 3) << 3;
            int gr = row0 + r;
            ra[i] = (gr < M) ? *(const uint4*)(A + (size_t)gr * K + k0 + c)
                             : make_uint4(0u, 0u, 0u, 0u);
            rw[i] = *(const uint4*)(Wp + (size_t)(col0 + r) * K + k0 + c);
        }
    };
    auto sts = [&](int buf) {
        #pragma unroll
        for (int i = 0; i < 2; i++) {
            int u = (i << 8) + tid;
            int r = u >> 2, c = (u & 3) << 3;
            *(uint4*)&As[buf][r][c] = ra[i];
            *(uint4*)&Ws[buf][r][c] = rw[i];
        }
    };

    loadg(0);
    sts(0);
    __syncthreads();

    const int a_r = (lane & 15);
    const int a_c = (lane >> 4) << 3;
    const int b_r = (lane & 7) + ((lane >> 4) << 3);
    const int b_c = ((lane >> 3) & 1) << 3;

    for (int it = 0; it < total; ++it) {
        int cur = it & 1;
        bool more = (it + 1 < total);
        if (more) loadg(it + 1);

        #pragma unroll
        for (int s = 0; s < 2; s++) {
            uint32_t afr[4][4], bfr[2][4];
            #pragma unroll
            for (int mt = 0; mt < 4; mt++)
                ldsm4(afr[mt], &As[cur][wm * 64 + mt * 16 + a_r][s * 16 + a_c]);
            #pragma unroll
            for (int p = 0; p < 2; p++)
                ldsm4(bfr[p], &Ws[cur][wn * 32 + p * 16 + b_r][s * 16 + b_c]);
            #pragma unroll
            for (int mt = 0; mt < 4; mt++)
                #pragma unroll
                for (int nt = 0; nt < 4; nt++)
                    mma_f16(acc[mt][nt], afr[mt],
                            bfr[nt >> 1][(nt & 1) * 2], bfr[nt >> 1][(nt & 1) * 2 + 1]);
        }

        if (more) sts(cur ^ 1);
        __syncthreads();
    }

    // ---- epilogue ----
    const int g = lane >> 2, t = lane & 3;
    #pragma unroll
    for (int mt = 0; mt < 4; mt++) {
        #pragma unroll
        for (int half = 0; half < 2; half++) {
            int r = row0 + wm * 64 + mt * 16 + g + half * 8;
            if (r >= M) continue;
            #pragma unroll
            for (int nt = 0; nt < 4; nt++) {
                int c = col0 + wn * 32 + nt * 8 + (t << 1);
                float v0 = acc[mt][nt][half * 2 + 0] + bias[c];
                float v1 = acc[mt][nt][half * 2 + 1] + bias[c + 1];
                if (EPI == 1) { v0 = seluf(v0); v1 = seluf(v1); }
                if (EPI == 2) {
                    float2 p = *(const float2*)(P + (size_t)(r >> 1) * HH + c);
                    v0 = p.x - seluf(v0);
                    v1 = p.y - seluf(v1);
                }
                if (OF32) *(float2*)(Cf + (size_t)r * N + c) = make_float2(v0, v1);
                if (OF16)
                    *(__half2*)(Cf16 + (size_t)r * N + c) = __floats2half2_rn(v0, v1);
            }
        }
    }
}

// ---------------------------------------------------------------------------
// 1-term fp16 GEMM (GRU gates): C = A[rowmap]@W^T + bias   (fp32 out)
// ---------------------------------------------------------------------------
__global__ __launch_bounds__(256, 2)
void hgemm1(const __half* __restrict__ A, const __half* __restrict__ W,
            const float* __restrict__ bias, float* __restrict__ Cf,
            int M, int N, int K, int ashift)
{
    __shared__ __half As[2][128][40];
    __shared__ __half Ws[2][128][40];

    const int tid = threadIdx.x;
    const int warp = tid >> 5, lane = tid & 31;
    const int wm = warp >> 2, wn = warp & 3;
    const int row0 = blockIdx.y * 128, col0 = blockIdx.x * 128;

    const int total = K >> 5;

    float acc[4][4][4];
    #pragma unroll
    for (int a = 0; a < 4; a++)
        #pragma unroll
        for (int b = 0; b < 4; b++)
            #pragma unroll
            for (int c = 0; c < 4; c++) acc[a][b][c] = 0.f;

    uint4 ra[2], rw[2];

    auto loadg = [&](int it) {
        int k0 = it << 5;
        #pragma unroll
        for (int i = 0; i < 2; i++) {
            int u = (i << 8) + tid;
            int r = u >> 2, c = (u & 3) << 3;
            int gr = row0 + r;
            ra[i] = (gr < M) ? *(const uint4*)(A + (size_t)(gr >> ashift) * K + k0 + c)
                             : make_uint4(0u, 0u, 0u, 0u);
            rw[i] = *(const uint4*)(W + (size_t)(col0 + r) * K + k0 + c);
        }
    };
    auto sts = [&](int buf) {
        #pragma unroll
        for (int i = 0; i < 2; i++) {
            int u = (i << 8) + tid;
            int r = u >> 2, c = (u & 3) << 3;
            *(uint4*)&As[buf][r][c] = ra[i];
            *(uint4*)&Ws[buf][r][c] = rw[i];
        }
    };

    loadg(0);
    sts(0);
    __syncthreads();

    const int a_r = (lane & 15);
    const int a_c = (lane >> 4) << 3;
    const int b_r = (lane & 7) + ((lane >> 4) << 3);
    const int b_c = ((lane >> 3) & 1) << 3;

    for (int it = 0; it < total; ++it) {
        int cur = it & 1;
        bool more = (it + 1 < total);
        if (more) loadg(it + 1);

        #pragma unroll
        for (int s = 0; s < 2; s++) {
            uint32_t afr[4][4], bfr[2][4];
            #pragma unroll
            for (int mt = 0; mt < 4; mt++)
                ldsm4(afr[mt], &As[cur][wm * 64 + mt * 16 + a_r][s * 16 + a_c]);
            #pragma unroll
            for (int p = 0; p < 2; p++)
                ldsm4(bfr[p], &Ws[cur][wn * 32 + p * 16 + b_r][s * 16 + b_c]);
            #pragma unroll
            for (int mt = 0; mt < 4; mt++)
                #pragma unroll
                for (int nt = 0; nt < 4; nt++)
                    mma_f16(acc[mt][nt], afr[mt],
                            bfr[nt >> 1][(nt & 1) * 2], bfr[nt >> 1][(nt & 1) * 2 + 1]);
        }

        if (more) sts(cur ^ 1);
        __syncthreads();
    }

    const int g = lane >> 2, t = lane & 3;
    #pragma unroll
    for (int mt = 0; mt < 4; mt++) {
        #pragma unroll
        for (int half = 0; half < 2; half++) {
            int r = row0 + wm * 64 + mt * 16 + g + half * 8;
            if (r >= M) continue;
            #pragma unroll
            for (int nt = 0; nt < 4; nt++) {
                int c = col0 + wn * 32 + nt * 8 + (t << 1);
                float v0 = acc[mt][nt][half * 2 + 0] + bias[c];
                float v1 = acc[mt][nt][half * 2 + 1] + bias[c + 1];
                *(float2*)(Cf + (size_t)r * N + c) = make_float2(v0, v1);
            }
        }
    }
}

// ---------------------------------------------------------------------------
// Split-K GEMM (small levels): partial sums only, no bias/epilogue.
//   TERMS=1: A@Wh^T over K.  TERMS=2: + A[:, :K2]@Wl^T.
//   Tile sequence (kt1 [+ kt2]) is divided evenly across gridDim.z splits.
//   Partials land in ws[split][M][N] (fp32). Deterministic, no atomics.
// ---------------------------------------------------------------------------
template<int TERMS>
__global__ __launch_bounds__(256, 2)
void hgemm_sk(const __half* __restrict__ A,
              const __half* __restrict__ Wh, const __half* __restrict__ Wl,
              float* __restrict__ ws,
              int M, int N, int K, int K2, int ashift)
{
    __shared__ __half As[2][128][40];
    __shared__ __half Ws[2][128][40];

    const int tid = threadIdx.x;
    const int warp = tid >> 5, lane = tid & 31;
    const int wm = warp >> 2, wn = warp & 3;
    const int row0 = blockIdx.y * 128, col0 = blockIdx.x * 128;

    const int kt1 = K >> 5;
    const int ktt = (TERMS == 2) ? kt1 + (K2 >> 5) : kt1;
    const int tps = ktt / gridDim.z;
    const int t0 = blockIdx.z * tps, t1 = t0 + tps;

    float acc[4][4][4];
    #pragma unroll
    for (int a = 0; a < 4; a++)
        #pragma unroll
        for (int b = 0; b < 4; b++)
            #pragma unroll
            for (int c = 0; c < 4; c++) acc[a][b][c] = 0.f;

    uint4 ra[2], rw[2];

    auto loadg = [&](int it) {
        int ph = (TERMS == 2 && it >= kt1) ? 1 : 0;
        int k0 = (it - (ph ? kt1 : 0)) << 5;
        const __half* Wp = ph ? Wl : Wh;
        #pragma unroll
        for (int i = 0; i < 2; i++) {
            int u = (i << 8) + tid;
            int r = u >> 2, c = (u & 3) << 3;
            int gr = row0 + r;
            ra[i] = (gr < M) ? *(const uint4*)(A + (size_t)(gr >> ashift) * K + k0 + c)
                             : make_uint4(0u, 0u, 0u, 0u);
            rw[i] = *(const uint4*)(Wp + (size_t)(col0 + r) * K + k0 + c);
        }
    };
    auto sts = [&](int buf) {
        #pragma unroll
        for (int i = 0; i < 2; i++) {
            int u = (i << 8) + tid;
            int r = u >> 2, c = (u & 3) << 3;
            *(uint4*)&As[buf][r][c] = ra[i];
            *(uint4*)&Ws[buf][r][c] = rw[i];
        }
    };

    loadg(t0);
    sts(0);
    __syncthreads();

    const int a_r = (lane & 15);
    const int a_c = (lane >> 4) << 3;
    const int b_r = (lane & 7) + ((lane >> 4) << 3);
    const int b_c = ((lane >> 3) & 1) << 3;

    for (int it = t0; it < t1; ++it) {
        int cur = (it - t0) & 1;
        bool more = (it + 1 < t1);
        if (more) loadg(it + 1);

        #pragma unroll
        for (int s = 0; s < 2; s++) {
            uint32_t afr[4][4], bfr[2][4];
            #pragma unroll
            for (int mt = 0; mt < 4; mt++)
                ldsm4(afr[mt], &As[cur][wm * 64 + mt * 16 + a_r][s * 16 + a_c]);
            #pragma unroll
            for (int p = 0; p < 2; p++)
                ldsm4(bfr[p], &Ws[cur][wn * 32 + p * 16 + b_r][s * 16 + b_c]);
            #pragma unroll
            for (int mt = 0; mt < 4; mt++)
                #pragma unroll
                for (int nt = 0; nt < 4; nt++)
                    mma_f16(acc[mt][nt], afr[mt],
                            bfr[nt >> 1][(nt & 1) * 2], bfr[nt >> 1][(nt & 1) * 2 + 1]);
        }

        if (more) sts(cur ^ 1);
        __syncthreads();
    }

    float* wp = ws + (size_t)blockIdx.z * M * N;
    const int g = lane >> 2, t = lane & 3;
    #pragma unroll
    for (int mt = 0; mt < 4; mt++) {
        #pragma unroll
        for (int half = 0; half < 2; half++) {
            int r = row0 + wm * 64 + mt * 16 + g + half * 8;
            if (r >= M) continue;
            #pragma unroll
            for (int nt = 0; nt < 4; nt++) {
                int c = col0 + wn * 32 + nt * 8 + (t << 1);
                *(float2*)(wp + (size_t)r * N + c) =
                    make_float2(acc[mt][nt][half * 2 + 0], acc[mt][nt][half * 2 + 1]);
            }
        }
    }
}

// Combine split-K partials: sum S slices, add bias, apply epilogue.
template<int EPI, bool OF32, bool OF16>
__global__ void sk_combine(const float* __restrict__ ws, int S,
                           const float* __restrict__ bias,
                           float* __restrict__ Cf, __half* __restrict__ Cf16,
                           int M, int N, const float* __restrict__ P)
{
    int i = blockIdx.x * blockDim.x + threadIdx.x;   // pair index over M*N/2
    if (i >= M * (N >> 1)) return;
    int r = (i << 1) / N, c = (i << 1) % N;
    size_t off = (size_t)r * N + c;
    float2 s = make_float2(0.f, 0.f);
    for (int k = 0; k < S; k++) {
        float2 v = *(const float2*)(ws + (size_t)k * M * N + off);
        s.x += v.x; s.y += v.y;
    }
    float v0 = s.x + bias[c], v1 = s.y + bias[c + 1];
    if (EPI == 1) { v0 = seluf(v0); v1 = seluf(v1); }
    if (EPI == 2) {
        float2 p = *(const float2*)(P + (size_t)(r >> 1) * HH + c);
        v0 = p.x - seluf(v0);
        v1 = p.y - seluf(v1);
    }
    if (OF32) *(float2*)(Cf + off) = make_float2(v0, v1);
    if (OF16) *(__half2*)(Cf16 + off) = __floats2half2_rn(v0, v1);
}

// ---------------------------------------------------------------------------
// Fused GRU + hb + depth + xh(fp16). Warp per row, 8 warps/block.
// ---------------------------------------------------------------------------
template<bool WRITE_XH, bool WRITE_HC>
__global__ void gru_fused(const float* __restrict__ gi, const float* __restrict__ gh,
                          const float* __restrict__ hcPrev, const float* __restrict__ xc,
                          const float* __restrict__ Whb, const float* __restrict__ bhb,
                          const float* __restrict__ dPrev, float* __restrict__ dOut,
                          float* __restrict__ hcOut, __half* __restrict__ hf16Out,
                          __half* __restrict__ xhf,
                          int M, int shift)
{
    const int m = blockIdx.x * 8 + (threadIdx.x >> 5);
    const int lane = threadIdx.x & 31;
    if (m >= M) return;
    const int p = m >> shift;
    const size_t o = (size_t)m * 768;
    const size_t hp = (size_t)p * RR;
    const size_t hm = (size_t)m * RR;

    float v[8];
    #pragma unroll
    for (int u = 0; u < 8; u++) {
        int j = lane + 32 * u;
        float ir = gi[o + j], iz = gi[o + 256 + j], inn = gi[o + 512 + j];
        float hr = gh[o + j], hz = gh[o + 256 + j], hn  = gh[o + 512 + j];
        float r = sigmoidf_(ir + hr);
        float z = sigmoidf_(iz + hz);
        float n = tanhf(inn + r * hn);
        float h = hcPrev[hp + j];
        float nv = (1.f - z) * n + z * h;
        v[u] = nv;
        if (WRITE_HC) {
            hcOut[hm + j] = nv;
            hf16Out[hm + j] = __float2half(nv);
        }
    }

    const float4* xr = (const float4*)(xc + (size_t)m * HH);
    const float4* w4 = (const float4*)Whb;
    float s = 0.f;
    #pragma unroll
    for (int i8 = 0; i8 < 8; i8++) {
        int i = lane + 32 * i8;
        float4 a = xr[i], b = w4[i];
        s += a.x * b.x + a.y * b.y + a.z * b.z + a.w * b.w;
        if (WRITE_XH) {
            size_t off = (size_t)m * (HH + RR) + i * 4;
            *(__half2*)(xhf + off)     = __floats2half2_rn(a.x, a.y);
            *(__half2*)(xhf + off + 2) = __floats2half2_rn(a.z, a.w);
        }
    }
    #pragma unroll
    for (int u = 0; u < 8; u++) {
        int j = lane + 32 * u;
        s += v[u] * Whb[1024 + j];
        if (WRITE_XH)
            xhf[(size_t)m * (HH + RR) + 1024 + j] = __float2half(v[u]);
    }
    #pragma unroll
    for (int off = 16; off; off >>= 1) s += __shfl_xor_sync(0xffffffffu, s, off);
    if (lane == 0) dOut[m] = dPrev[p] + sigmoidf_(s + bhb[0]);
}

// ---------------------------------------------------------------------------
// Misc elementwise kernels
// ---------------------------------------------------------------------------
__global__ void half_split_kernel(const float* __restrict__ in, __half* __restrict__ h,
                                  __half* __restrict__ l, int n) {
    int i = blockIdx.x * blockDim.x + threadIdx.x;
    if (i < n) {
        __half hv = __float2half(in[i]);
        h[i] = hv;
        l[i] = __float2half(in[i] - __half2float(hv));
    }
}
__global__ void half_cast_kernel(const float* __restrict__ in, __half* __restrict__ out, int n) {
    int i = blockIdx.x * blockDim.x + threadIdx.x;
    if (i < n) out[i] = __float2half(in[i]);
}
__global__ void selu_half_kernel(const float* __restrict__ in, __half* __restrict__ out, int n) {
    int i = blockIdx.x * blockDim.x + threadIdx.x;
    if (i < n) out[i] = __float2half(seluf(in[i]));
}
__global__ void mean_kernel(const float* __restrict__ y, float* __restrict__ xc,
                            __half* __restrict__ xf16) {
    int i = blockIdx.x * blockDim.x + threadIdx.x;
    if (i >= BB * HH) return;
    int b = i >> 10, h = i & (HH - 1);
    float s = 0.f;
    #pragma unroll 8
    for (int t = 0; t < SS; t++) s += y[((size_t)(b * SS + t)) * HH + h];
    float v = s * (1.f / SS);
    xc[i] = v;
    xf16[i] = __float2half(v);
}
__global__ void zero32_kernel(uint32_t* p, int n) {
    int i = blockIdx.x * blockDim.x + threadIdx.x;
    if (i < n) p[i] = 0u;
}
__global__ void out_kernel(const float* __restrict__ xc, const float* __restrict__ dep,
                           float* __restrict__ out) {
    int i = blockIdx.x * blockDim.x + threadIdx.x;
    if (i >= MAXM * (HH + 1)) return;
    int m = i / (HH + 1), k = i - m * (HH + 1);
    out[i] = (k < HH) ? xc[(size_t)m * HH + k] : dep[m];
}

// ---------------------------------------------------------------------------
// Host driver (graph-capturable: only kernel launches)
// ---------------------------------------------------------------------------
static inline int cdiv(int a, int b) { return (a + b - 1) / b; }

extern "C" void kernel_launch(void* const* d_in, const int* in_sizes, int n_in,
                              void* d_out, int out_size)
{
    const float* x        = (const float*)d_in[0];
    const float* W_hidden = (const float*)d_in[1];
    const float* b_hidden = (const float*)d_in[2];
    const float* W_hb     = (const float*)d_in[3];
    const float* b_hb     = (const float*)d_in[4];
    const float* W_branch = (const float*)d_in[5];
    const float* b_branch = (const float*)d_in[6];
    const float* W_ih     = (const float*)d_in[7];
    const float* W_hh     = (const float*)d_in[8];
    const float* b_ih     = (const float*)d_in[9];
    const float* b_hh     = (const float*)d_in[10];

    float *xcA, *xcB, *hcA, *hcB, *dA, *dB, *gi, *gh, *y, *ws;
    __half *xcf16, *hf16A, *hf16B, *sxf, *xhf, *lrf;
    __half *Whidh, *Whidl, *Wbrh, *Wbrl, *Wihf, *Whhf;

    cudaGetSymbolAddress((void**)&xcA, g_xcA);   cudaGetSymbolAddress((void**)&xcB, g_xcB);
    cudaGetSymbolAddress((void**)&hcA, g_hcA);   cudaGetSymbolAddress((void**)&hcB, g_hcB);
    cudaGetSymbolAddress((void**)&dA,  g_dA);    cudaGetSymbolAddress((void**)&dB,  g_dB);
    cudaGetSymbolAddress((void**)&gi,  g_gi);    cudaGetSymbolAddress((void**)&gh,  g_gh);
    cudaGetSymbolAddress((void**)&y,   g_y);     cudaGetSymbolAddress((void**)&ws,  g_ws);
    cudaGetSymbolAddress((void**)&xcf16, g_xcf16);
    cudaGetSymbolAddress((void**)&hf16A, g_hf16A); cudaGetSymbolAddress((void**)&hf16B, g_hf16B);
    cudaGetSymbolAddress((void**)&sxf, g_sxf);
    cudaGetSymbolAddress((void**)&xhf, g_xhf);
    cudaGetSymbolAddress((void**)&lrf, g_lrf);
    cudaGetSymbolAddress((void**)&Whidh, g_Whidh); cudaGetSymbolAddress((void**)&Whidl, g_Whidl);
    cudaGetSymbolAddress((void**)&Wbrh, g_Wbrh);   cudaGetSymbolAddress((void**)&Wbrl, g_Wbrl);
    cudaGetSymbolAddress((void**)&Wihf, g_Wihf);   cudaGetSymbolAddress((void**)&Whhf, g_Whhf);

    const int nsx = BB * SS * HH;

    // ---- weight prep ----
    half_split_kernel<<<cdiv(HH*HH, 256), 256>>>(W_hidden, Whidh, Whidl, HH*HH);
    half_split_kernel<<<cdiv(2*HH*(HH+RR), 256), 256>>>(W_branch, Wbrh, Wbrl, 2*HH*(HH+RR));
    half_cast_kernel<<<cdiv(3*RR*HH, 256), 256>>>(W_ih, Wihf, 3*RR*HH);
    half_cast_kernel<<<cdiv(3*RR*RR, 256), 256>>>(W_hh, Whhf, 3*RR*RR);

    // ---- root: xc0 = mean_s selu(selu(x) @ W_hidden^T + b_hidden) ----
    selu_half_kernel<<<cdiv(nsx, 256), 256>>>(x, sxf, nsx);
    hgemm2<1, true, false><<<dim3(HH/128, (BB*SS)/128), 256>>>(
        sxf, Whidh, Whidl, b_hidden, y, nullptr, BB*SS, HH, HH, HH, nullptr);
    mean_kernel<<<cdiv(BB*HH, 256), 256>>>(y, xcA, xcf16);

    zero32_kernel<<<cdiv(BB*RR, 256), 256>>>((uint32_t*)hcA, BB*RR);
    zero32_kernel<<<cdiv(BB*RR/2, 256), 256>>>((uint32_t*)hf16A, BB*RR/2);
    zero32_kernel<<<1, 64>>>((uint32_t*)dA, BB);

    // ---- levels 0 .. DEPTH-1 ----
    for (int d = 0; d < DEPTH; d++) {
        int M  = BB << d;
        int M2 = M << 1;
        int gy = cdiv(M, 128);
        int shift = (d == 0) ? 0 : 1;
        int S = (d <= 3) ? 8 : ((d == 4) ? 4 : 2);

        // gi = xc @ W_ih^T  (split-K while the chip is underutilized)
        if (d <= 6) {
            hgemm_sk<1><<<dim3(6, gy, S), 256>>>(xcf16, Wihf, Wihf, ws, M, 768, HH, 0, 0);
            sk_combine<0, true, false><<<cdiv(M*768/2, 256), 256>>>(
                ws, S, b_ih, gi, nullptr, M, 768, nullptr);
        } else {
            hgemm1<<<dim3(6, gy), 256>>>(xcf16, Wihf, b_ih, gi, M, 768, HH, 0);
        }

        // gh = hc[parent] @ W_hh^T  (short K; plain)
        hgemm1<<<dim3(6, gy), 256>>>(hf16A, Whhf, b_hh, gh, M, 768, RR, shift);

        gru_fused<true, true><<<cdiv(M, 8), 256>>>(
            gi, gh, hcA, xcA, W_hb, b_hb, dA, dB,
            hcB, hf16B, xhf, M, shift);

        // branch = selu(xh @ (Wbrh + Wbrl[:, :1024])^T + b)  -> fp16 lr
        if (d <= 5) {
            hgemm_sk<2><<<dim3(16, gy, S), 256>>>(xhf, Wbrh, Wbrl, ws, M, 2*HH, HH+RR, HH, 0);
            sk_combine<1, false, true><<<cdiv(M*2*HH/2, 256), 256>>>(
                ws, S, b_branch, nullptr, lrf, M, 2*HH, nullptr);
        } else {
            hgemm2<1, false, true><<<dim3(16, gy), 256>>>(
                xhf, Wbrh, Wbrl, b_branch, nullptr, lrf, M, 2*HH, HH+RR, HH, nullptr);
        }

        // child = xc[parent] - selu(lr @ (Whid hi+lo)^T + b)  -> fp32 + fp16
        if (d <= 5) {
            hgemm_sk<2><<<dim3(8, cdiv(M2, 128), S), 256>>>(lrf, Whidh, Whidl, ws, M2, HH, HH, HH, 0);
            sk_combine<2, true, true><<<cdiv(M2*HH/2, 256), 256>>>(
                ws, S, b_hidden, xcB, xcf16, M2, HH, xcA);
        } else {
            hgemm2<2, true, true><<<dim3(8, cdiv(M2, 128)), 256>>>(
                lrf, Whidh, Whidl, b_hidden, xcB, xcf16, M2, HH, HH, HH, xcA);
        }

        float* t; __half* ht;
        t = xcA; xcA = xcB; xcB = t;
        t = hcA; hcA = hcB; hcB = t;
        t = dA;  dA  = dB;  dB  = t;
        ht = hf16A; hf16A = hf16B; hf16B = ht;
    }

    // ---- leaf step (M = 32768): GRU + hb only ----
    {
        int M = MAXM;
        int gy = M / 128;
        hgemm1<<<dim3(6, gy), 256>>>(xcf16, Wihf, b_ih, gi, M, 768, HH, 0);
        hgemm1<<<dim3(6, gy), 256>>>(hf16A, Whhf, b_hh, gh, M, 768, RR, 1);
        gru_fused<false, false><<<cdiv(M, 8), 256>>>(
            gi, gh, hcA, xcA, W_hb, b_hb, dA, dB,
            nullptr, nullptr, nullptr, M, 1);
        out_kernel<<<cdiv(M*(HH+1), 256), 256>>>(xcA, dB, (float*)d_out);
    }
}

// round 14
// speedup vs baseline: 4.1234x; 1.1587x over previous
#include <cuda_runtime.h>
#include <cuda_fp16.h>
#include <math.h>
#include <stdint.h>

// ---------------------------------------------------------------------------
// Problem constants
// ---------------------------------------------------------------------------
#define BB   64
#define SS   32
#define HH   1024
#define RR   256
#define DEPTH 9
#define MAXM (BB*512)

#define SELU_SCALE 1.0507009873554805f
#define SELU_ALPHA 1.6732632423543772f

__device__ __forceinline__ float seluf(float v) {
    return v > 0.f ? SELU_SCALE * v : SELU_SCALE * SELU_ALPHA * expm1f(v);
}
__device__ __forceinline__ float sigmoidf_(float v) {
    return 1.f / (1.f + __expf(-v));
}

// ---------------------------------------------------------------------------
// Scratch (device globals; allocation is forbidden)
// ---------------------------------------------------------------------------
__device__ float g_xcA[(size_t)MAXM * HH];
__device__ float g_xcB[(size_t)MAXM * HH];
__device__ float g_hcA[(size_t)MAXM * RR];
__device__ float g_hcB[(size_t)MAXM * RR];
__device__ float g_dA[MAXM];
__device__ float g_dB[MAXM];
__device__ float g_y [(size_t)BB * SS * HH];
__device__ float g_ws[(size_t)8388608];          // split-K workspace (32 MB)
__device__ __half g_gif[(size_t)MAXM * 3 * RR];
__device__ __half g_ghf[(size_t)MAXM * 3 * RR];
__device__ __half g_xcf16[(size_t)MAXM * HH];
__device__ __half g_hf16A[(size_t)MAXM * RR];
__device__ __half g_hf16B[(size_t)MAXM * RR];
__device__ __half g_sxf[(size_t)BB * SS * HH];
__device__ __half g_xhf[(size_t)MAXM * (HH + RR)];
__device__ __half g_lrf[(size_t)MAXM * HH];      // branch out viewed [2M,1024]
// weights (fp16 hi/lo for the 2-term GEMMs; single fp16 for GRU/child)
__device__ __half g_Whidh[HH * HH];
__device__ __half g_Whidl[HH * HH];
__device__ __half g_Wbrh[2 * HH * (HH + RR)];
__device__ __half g_Wbrl[2 * HH * (HH + RR)];
__device__ __half g_Wihf[3 * RR * HH];
__device__ __half g_Whhf[3 * RR * RR];

// ---------------------------------------------------------------------------
// mma.sync helpers
// ---------------------------------------------------------------------------
__device__ __forceinline__ void ldsm4(uint32_t* r, const void* p) {
    uint32_t a = (uint32_t)__cvta_generic_to_shared(p);
    asm volatile("ldmatrix.sync.aligned.m8n8.x4.shared.b16 {%0,%1,%2,%3}, [%4];"
        : "=r"(r[0]), "=r"(r[1]), "=r"(r[2]), "=r"(r[3]) : "r"(a));
}
__device__ __forceinline__ void mma_f16(float* d, const uint32_t* a, uint32_t b0, uint32_t b1) {
    asm volatile("mma.sync.aligned.m16n8k16.row.col.f32.f16.f16.f32 "
        "{%0,%1,%2,%3}, {%4,%5,%6,%7}, {%8,%9}, {%0,%1,%2,%3};"
        : "+f"(d[0]), "+f"(d[1]), "+f"(d[2]), "+f"(d[3])
        : "r"(a[0]), "r"(a[1]), "r"(a[2]), "r"(a[3]), "r"(b0), "r"(b1));
}

// ---------------------------------------------------------------------------
// 2-term fp16 GEMM: C[M,N] = epi( A@Wh^T + A[:, :K2]@Wl[:, :K2]^T + bias )
//   K2 = 0 -> single-term (hi weights only).
//   EPI 0: bias   EPI 1: selu   EPI 2: P[r>>1] - selu
// 128x128 CTA tile, 8 warps of 64x32, double-buffered smem.
// ---------------------------------------------------------------------------
template<int EPI, bool OF32, bool OF16>
__global__ __launch_bounds__(256, 2)
void hgemm2(const __half* __restrict__ A,
            const __half* __restrict__ Wh, const __half* __restrict__ Wl,
            const float* __restrict__ bias,
            float* __restrict__ Cf, __half* __restrict__ Cf16,
            int M, int N, int K, int K2, int ashift, const float* __restrict__ P)
{
    __shared__ __half As[2][128][40];
    __shared__ __half Ws[2][128][40];

    const int tid = threadIdx.x;
    const int warp = tid >> 5, lane = tid & 31;
    const int wm = warp >> 2, wn = warp & 3;      // 2 x 4 warp grid
    const int row0 = blockIdx.y * 128, col0 = blockIdx.x * 128;

    const int kt1 = K >> 5;
    const int total = kt1 + (K2 >> 5);

    float acc[4][4][4];
    #pragma unroll
    for (int a = 0; a < 4; a++)
        #pragma unroll
        for (int b = 0; b < 4; b++)
            #pragma unroll
            for (int c = 0; c < 4; c++) acc[a][b][c] = 0.f;

    uint4 ra[2], rw[2];

    auto loadg = [&](int it) {
        int ph = (it >= kt1) ? 1 : 0;
        int k0 = (it - (ph ? kt1 : 0)) << 5;
        const __half* Wp = ph ? Wl : Wh;
        #pragma unroll
        for (int i = 0; i < 2; i++) {
            int u = (i << 8) + tid;
            int r = u >> 2, c = (u & 3) << 3;
            int gr = row0 + r;
            ra[i] = (gr < M) ? *(const uint4*)(A + (size_t)(gr >> ashift) * K + k0 + c)
                             : make_uint4(0u, 0u, 0u, 0u);
            rw[i] = *(const uint4*)(Wp + (size_t)(col0 + r) * K + k0 + c);
        }
    };
    auto sts = [&](int buf) {
        #pragma unroll
        for (int i = 0; i < 2; i++) {
            int u = (i << 8) + tid;
            int r = u >> 2, c = (u & 3) << 3;
            *(uint4*)&As[buf][r][c] = ra[i];
            *(uint4*)&Ws[buf][r][c] = rw[i];
        }
    };

    loadg(0);
    sts(0);
    __syncthreads();

    const int a_r = (lane & 15);
    const int a_c = (lane >> 4) << 3;
    const int b_r = (lane & 7) + ((lane >> 4) << 3);
    const int b_c = ((lane >> 3) & 1) << 3;

    for (int it = 0; it < total; ++it) {
        int cur = it & 1;
        bool more = (it + 1 < total);
        if (more) loadg(it + 1);

        #pragma unroll
        for (int s = 0; s < 2; s++) {
            uint32_t afr[4][4], bfr[2][4];
            #pragma unroll
            for (int mt = 0; mt < 4; mt++)
                ldsm4(afr[mt], &As[cur][wm * 64 + mt * 16 + a_r][s * 16 + a_c]);
            #pragma unroll
            for (int p = 0; p < 2; p++)
                ldsm4(bfr[p], &Ws[cur][wn * 32 + p * 16 + b_r][s * 16 + b_c]);
            #pragma unroll
            for (int mt = 0; mt < 4; mt++)
                #pragma unroll
                for (int nt = 0; nt < 4; nt++)
                    mma_f16(acc[mt][nt], afr[mt],
                            bfr[nt >> 1][(nt & 1) * 2], bfr[nt >> 1][(nt & 1) * 2 + 1]);
        }

        if (more) sts(cur ^ 1);
        __syncthreads();
    }

    // ---- epilogue ----
    const int g = lane >> 2, t = lane & 3;
    #pragma unroll
    for (int mt = 0; mt < 4; mt++) {
        #pragma unroll
        for (int half = 0; half < 2; half++) {
            int r = row0 + wm * 64 + mt * 16 + g + half * 8;
            if (r >= M) continue;
            #pragma unroll
            for (int nt = 0; nt < 4; nt++) {
                int c = col0 + wn * 32 + nt * 8 + (t << 1);
                float v0 = acc[mt][nt][half * 2 + 0] + bias[c];
                float v1 = acc[mt][nt][half * 2 + 1] + bias[c + 1];
                if (EPI == 1) { v0 = seluf(v0); v1 = seluf(v1); }
                if (EPI == 2) {
                    float2 p = *(const float2*)(P + (size_t)(r >> 1) * HH + c);
                    v0 = p.x - seluf(v0);
                    v1 = p.y - seluf(v1);
                }
                if (OF32) *(float2*)(Cf + (size_t)r * N + c) = make_float2(v0, v1);
                if (OF16)
                    *(__half2*)(Cf16 + (size_t)r * N + c) = __floats2half2_rn(v0, v1);
            }
        }
    }
}

// ---------------------------------------------------------------------------
// Split-K GEMM (small levels): partial sums only, no bias/epilogue.
//   TERMS=1: A@Wh^T over K.  TERMS=2: + A[:, :K2]@Wl^T (K2 may be 0).
//   Partials land in ws[split][M][N] (fp32). Deterministic, no atomics.
// ---------------------------------------------------------------------------
template<int TERMS>
__global__ __launch_bounds__(256, 2)
void hgemm_sk(const __half* __restrict__ A,
              const __half* __restrict__ Wh, const __half* __restrict__ Wl,
              float* __restrict__ ws,
              int M, int N, int K, int K2, int ashift)
{
    __shared__ __half As[2][128][40];
    __shared__ __half Ws[2][128][40];

    const int tid = threadIdx.x;
    const int warp = tid >> 5, lane = tid & 31;
    const int wm = warp >> 2, wn = warp & 3;
    const int row0 = blockIdx.y * 128, col0 = blockIdx.x * 128;

    const int kt1 = K >> 5;
    const int ktt = (TERMS == 2) ? kt1 + (K2 >> 5) : kt1;
    const int tps = ktt / gridDim.z;
    const int t0 = blockIdx.z * tps, t1 = t0 + tps;

    float acc[4][4][4];
    #pragma unroll
    for (int a = 0; a < 4; a++)
        #pragma unroll
        for (int b = 0; b < 4; b++)
            #pragma unroll
            for (int c = 0; c < 4; c++) acc[a][b][c] = 0.f;

    uint4 ra[2], rw[2];

    auto loadg = [&](int it) {
        int ph = (TERMS == 2 && it >= kt1) ? 1 : 0;
        int k0 = (it - (ph ? kt1 : 0)) << 5;
        const __half* Wp = ph ? Wl : Wh;
        #pragma unroll
        for (int i = 0; i < 2; i++) {
            int u = (i << 8) + tid;
            int r = u >> 2, c = (u & 3) << 3;
            int gr = row0 + r;
            ra[i] = (gr < M) ? *(const uint4*)(A + (size_t)(gr >> ashift) * K + k0 + c)
                             : make_uint4(0u, 0u, 0u, 0u);
            rw[i] = *(const uint4*)(Wp + (size_t)(col0 + r) * K + k0 + c);
        }
    };
    auto sts = [&](int buf) {
        #pragma unroll
        for (int i = 0; i < 2; i++) {
            int u = (i << 8) + tid;
            int r = u >> 2, c = (u & 3) << 3;
            *(uint4*)&As[buf][r][c] = ra[i];
            *(uint4*)&Ws[buf][r][c] = rw[i];
        }
    };

    loadg(t0);
    sts(0);
    __syncthreads();

    const int a_r = (lane & 15);
    const int a_c = (lane >> 4) << 3;
    const int b_r = (lane & 7) + ((lane >> 4) << 3);
    const int b_c = ((lane >> 3) & 1) << 3;

    for (int it = t0; it < t1; ++it) {
        int cur = (it - t0) & 1;
        bool more = (it + 1 < t1);
        if (more) loadg(it + 1);

        #pragma unroll
        for (int s = 0; s < 2; s++) {
            uint32_t afr[4][4], bfr[2][4];
            #pragma unroll
            for (int mt = 0; mt < 4; mt++)
                ldsm4(afr[mt], &As[cur][wm * 64 + mt * 16 + a_r][s * 16 + a_c]);
            #pragma unroll
            for (int p = 0; p < 2; p++)
                ldsm4(bfr[p], &Ws[cur][wn * 32 + p * 16 + b_r][s * 16 + b_c]);
            #pragma unroll
            for (int mt = 0; mt < 4; mt++)
                #pragma unroll
                for (int nt = 0; nt < 4; nt++)
                    mma_f16(acc[mt][nt], afr[mt],
                            bfr[nt >> 1][(nt & 1) * 2], bfr[nt >> 1][(nt & 1) * 2 + 1]);
        }

        if (more) sts(cur ^ 1);
        __syncthreads();
    }

    float* wp = ws + (size_t)blockIdx.z * M * N;
    const int g = lane >> 2, t = lane & 3;
    #pragma unroll
    for (int mt = 0; mt < 4; mt++) {
        #pragma unroll
        for (int half = 0; half < 2; half++) {
            int r = row0 + wm * 64 + mt * 16 + g + half * 8;
            if (r >= M) continue;
            #pragma unroll
            for (int nt = 0; nt < 4; nt++) {
                int c = col0 + wn * 32 + nt * 8 + (t << 1);
                *(float2*)(wp + (size_t)r * N + c) =
                    make_float2(acc[mt][nt][half * 2 + 0], acc[mt][nt][half * 2 + 1]);
            }
        }
    }
}

// Combine split-K partials: sum S slices, add bias, apply epilogue.
template<int EPI, bool OF32, bool OF16>
__global__ void sk_combine(const float* __restrict__ ws, int S,
                           const float* __restrict__ bias,
                           float* __restrict__ Cf, __half* __restrict__ Cf16,
                           int M, int N, const float* __restrict__ P)
{
    int i = blockIdx.x * blockDim.x + threadIdx.x;   // pair index over M*N/2
    if (i >= M * (N >> 1)) return;
    int r = (i << 1) / N, c = (i << 1) % N;
    size_t off = (size_t)r * N + c;
    float2 s = make_float2(0.f, 0.f);
    for (int k = 0; k < S; k++) {
        float2 v = *(const float2*)(ws + (size_t)k * M * N + off);
        s.x += v.x; s.y += v.y;
    }
    float v0 = s.x + bias[c], v1 = s.y + bias[c + 1];
    if (EPI == 1) { v0 = seluf(v0); v1 = seluf(v1); }
    if (EPI == 2) {
        float2 p = *(const float2*)(P + (size_t)(r >> 1) * HH + c);
        v0 = p.x - seluf(v0);
        v1 = p.y - seluf(v1);
    }
    if (OF32) *(float2*)(Cf + off) = make_float2(v0, v1);
    if (OF16) *(__half2*)(Cf16 + off) = __floats2half2_rn(v0, v1);
}

// ---------------------------------------------------------------------------
// Fused GRU + hb + depth + xh(fp16). Warp per row, 8 warps/block.
// Gates (gi/gh) are fp16.
// ---------------------------------------------------------------------------
template<bool WRITE_XH, bool WRITE_HC>
__global__ void gru_fused(const __half* __restrict__ gi, const __half* __restrict__ gh,
                          const float* __restrict__ hcPrev, const float* __restrict__ xc,
                          const float* __restrict__ Whb, const float* __restrict__ bhb,
                          const float* __restrict__ dPrev, float* __restrict__ dOut,
                          float* __restrict__ hcOut, __half* __restrict__ hf16Out,
                          __half* __restrict__ xhf,
                          int M, int shift)
{
    const int m = blockIdx.x * 8 + (threadIdx.x >> 5);
    const int lane = threadIdx.x & 31;
    if (m >= M) return;
    const int p = m >> shift;
    const size_t o = (size_t)m * 768;
    const size_t hp = (size_t)p * RR;
    const size_t hm = (size_t)m * RR;

    float v[8];
    #pragma unroll
    for (int u = 0; u < 8; u++) {
        int j = lane + 32 * u;
        float ir = __half2float(gi[o + j]);
        float iz = __half2float(gi[o + 256 + j]);
        float inn = __half2float(gi[o + 512 + j]);
        float hr = __half2float(gh[o + j]);
        float hz = __half2float(gh[o + 256 + j]);
        float hn = __half2float(gh[o + 512 + j]);
        float r = sigmoidf_(ir + hr);
        float z = sigmoidf_(iz + hz);
        float n = tanhf(inn + r * hn);
        float h = hcPrev[hp + j];
        float nv = (1.f - z) * n + z * h;
        v[u] = nv;
        if (WRITE_HC) {
            hcOut[hm + j] = nv;
            hf16Out[hm + j] = __float2half(nv);
        }
    }

    const float4* xr = (const float4*)(xc + (size_t)m * HH);
    const float4* w4 = (const float4*)Whb;
    float s = 0.f;
    #pragma unroll
    for (int i8 = 0; i8 < 8; i8++) {
        int i = lane + 32 * i8;
        float4 a = xr[i], b = w4[i];
        s += a.x * b.x + a.y * b.y + a.z * b.z + a.w * b.w;
        if (WRITE_XH) {
            size_t off = (size_t)m * (HH + RR) + i * 4;
            *(__half2*)(xhf + off)     = __floats2half2_rn(a.x, a.y);
            *(__half2*)(xhf + off + 2) = __floats2half2_rn(a.z, a.w);
        }
    }
    #pragma unroll
    for (int u = 0; u < 8; u++) {
        int j = lane + 32 * u;
        s += v[u] * Whb[1024 + j];
        if (WRITE_XH)
            xhf[(size_t)m * (HH + RR) + 1024 + j] = __float2half(v[u]);
    }
    #pragma unroll
    for (int off = 16; off; off >>= 1) s += __shfl_xor_sync(0xffffffffu, s, off);
    if (lane == 0) dOut[m] = dPrev[p] + sigmoidf_(s + bhb[0]);
}

// ---------------------------------------------------------------------------
// Misc elementwise kernels
// ---------------------------------------------------------------------------
__global__ void half_split_kernel(const float* __restrict__ in, __half* __restrict__ h,
                                  __half* __restrict__ l, int n) {
    int i = blockIdx.x * blockDim.x + threadIdx.x;
    if (i < n) {
        __half hv = __float2half(in[i]);
        h[i] = hv;
        l[i] = __float2half(in[i] - __half2float(hv));
    }
}
__global__ void half_cast_kernel(const float* __restrict__ in, __half* __restrict__ out, int n) {
    int i = blockIdx.x * blockDim.x + threadIdx.x;
    if (i < n) out[i] = __float2half(in[i]);
}
__global__ void selu_half_kernel(const float* __restrict__ in, __half* __restrict__ out, int n) {
    int i = blockIdx.x * blockDim.x + threadIdx.x;
    if (i < n) out[i] = __float2half(seluf(in[i]));
}
__global__ void mean_kernel(const float* __restrict__ y, float* __restrict__ xc,
                            __half* __restrict__ xf16) {
    int i = blockIdx.x * blockDim.x + threadIdx.x;
    if (i >= BB * HH) return;
    int b = i >> 10, h = i & (HH - 1);
    float s = 0.f;
    #pragma unroll 8
    for (int t = 0; t < SS; t++) s += y[((size_t)(b * SS + t)) * HH + h];
    float v = s * (1.f / SS);
    xc[i] = v;
    xf16[i] = __float2half(v);
}
__global__ void zero32_kernel(uint32_t* p, int n) {
    int i = blockIdx.x * blockDim.x + threadIdx.x;
    if (i < n) p[i] = 0u;
}
__global__ void out_kernel(const float* __restrict__ xc, const float* __restrict__ dep,
                           float* __restrict__ out) {
    int i = blockIdx.x * blockDim.x + threadIdx.x;
    if (i >= MAXM * (HH + 1)) return;
    int m = i / (HH + 1), k = i - m * (HH + 1);
    out[i] = (k < HH) ? xc[(size_t)m * HH + k] : dep[m];
}

// ---------------------------------------------------------------------------
// Host driver (graph-capturable: only kernel launches)
// ---------------------------------------------------------------------------
static inline int cdiv(int a, int b) { return (a + b - 1) / b; }

extern "C" void kernel_launch(void* const* d_in, const int* in_sizes, int n_in,
                              void* d_out, int out_size)
{
    const float* x        = (const float*)d_in[0];
    const float* W_hidden = (const float*)d_in[1];
    const float* b_hidden = (const float*)d_in[2];
    const float* W_hb     = (const float*)d_in[3];
    const float* b_hb     = (const float*)d_in[4];
    const float* W_branch = (const float*)d_in[5];
    const float* b_branch = (const float*)d_in[6];
    const float* W_ih     = (const float*)d_in[7];
    const float* W_hh     = (const float*)d_in[8];
    const float* b_ih     = (const float*)d_in[9];
    const float* b_hh     = (const float*)d_in[10];

    float *xcA, *xcB, *hcA, *hcB, *dA, *dB, *y, *ws;
    __half *gif, *ghf, *xcf16, *hf16A, *hf16B, *sxf, *xhf, *lrf;
    __half *Whidh, *Whidl, *Wbrh, *Wbrl, *Wihf, *Whhf;

    cudaGetSymbolAddress((void**)&xcA, g_xcA);   cudaGetSymbolAddress((void**)&xcB, g_xcB);
    cudaGetSymbolAddress((void**)&hcA, g_hcA);   cudaGetSymbolAddress((void**)&hcB, g_hcB);
    cudaGetSymbolAddress((void**)&dA,  g_dA);    cudaGetSymbolAddress((void**)&dB,  g_dB);
    cudaGetSymbolAddress((void**)&y,   g_y);     cudaGetSymbolAddress((void**)&ws,  g_ws);
    cudaGetSymbolAddress((void**)&gif, g_gif);   cudaGetSymbolAddress((void**)&ghf, g_ghf);
    cudaGetSymbolAddress((void**)&xcf16, g_xcf16);
    cudaGetSymbolAddress((void**)&hf16A, g_hf16A); cudaGetSymbolAddress((void**)&hf16B, g_hf16B);
    cudaGetSymbolAddress((void**)&sxf, g_sxf);
    cudaGetSymbolAddress((void**)&xhf, g_xhf);
    cudaGetSymbolAddress((void**)&lrf, g_lrf);
    cudaGetSymbolAddress((void**)&Whidh, g_Whidh); cudaGetSymbolAddress((void**)&Whidl, g_Whidl);
    cudaGetSymbolAddress((void**)&Wbrh, g_Wbrh);   cudaGetSymbolAddress((void**)&Wbrl, g_Wbrl);
    cudaGetSymbolAddress((void**)&Wihf, g_Wihf);   cudaGetSymbolAddress((void**)&Whhf, g_Whhf);

    const int nsx = BB * SS * HH;

    // ---- weight prep ----
    half_split_kernel<<<cdiv(HH*HH, 256), 256>>>(W_hidden, Whidh, Whidl, HH*HH);
    half_split_kernel<<<cdiv(2*HH*(HH+RR), 256), 256>>>(W_branch, Wbrh, Wbrl, 2*HH*(HH+RR));
    half_cast_kernel<<<cdiv(3*RR*HH, 256), 256>>>(W_ih, Wihf, 3*RR*HH);
    half_cast_kernel<<<cdiv(3*RR*RR, 256), 256>>>(W_hh, Whhf, 3*RR*RR);

    // ---- root: xc0 = mean_s selu(selu(x) @ W_hidden^T + b_hidden) ----
    selu_half_kernel<<<cdiv(nsx, 256), 256>>>(x, sxf, nsx);
    hgemm2<1, true, false><<<dim3(HH/128, (BB*SS)/128), 256>>>(
        sxf, Whidh, Whidl, b_hidden, y, nullptr, BB*SS, HH, HH, HH, 0, nullptr);
    mean_kernel<<<cdiv(BB*HH, 256), 256>>>(y, xcA, xcf16);

    zero32_kernel<<<cdiv(BB*RR, 256), 256>>>((uint32_t*)hcA, BB*RR);
    zero32_kernel<<<cdiv(BB*RR/2, 256), 256>>>((uint32_t*)hf16A, BB*RR/2);
    zero32_kernel<<<1, 64>>>((uint32_t*)dA, BB);

    // ---- levels 0 .. DEPTH-1 ----
    for (int d = 0; d < DEPTH; d++) {
        int M  = BB << d;
        int M2 = M << 1;
        int gy = cdiv(M, 128);
        int shift = (d == 0) ? 0 : 1;
        int S = (d <= 3) ? 8 : ((d == 4) ? 4 : 2);

        // gi = xc @ W_ih^T  (split-K while the chip is underutilized) -> fp16
        if (d <= 6) {
            hgemm_sk<1><<<dim3(6, gy, S), 256>>>(xcf16, Wihf, Wihf, ws, M, 768, HH, 0, 0);
            sk_combine<0, false, true><<<cdiv(M*768/2, 256), 256>>>(
                ws, S, b_ih, nullptr, gif, M, 768, nullptr);
        } else {
            hgemm2<0, false, true><<<dim3(6, gy), 256>>>(
                xcf16, Wihf, Wihf, b_ih, nullptr, gif, M, 768, HH, 0, 0, nullptr);
        }

        // gh = hc[parent] @ W_hh^T  (short K; plain) -> fp16
        hgemm2<0, false, true><<<dim3(6, gy), 256>>>(
            hf16A, Whhf, Whhf, b_hh, nullptr, ghf, M, 768, RR, 0, shift, nullptr);

        gru_fused<true, true><<<cdiv(M, 8), 256>>>(
            gif, ghf, hcA, xcA, W_hb, b_hb, dA, dB,
            hcB, hf16B, xhf, M, shift);

        // branch = selu(xh @ (Wbrh + Wbrl[:, :1024])^T + b)  -> fp16 lr
        if (d <= 5) {
            hgemm_sk<2><<<dim3(16, gy, S), 256>>>(xhf, Wbrh, Wbrl, ws, M, 2*HH, HH+RR, HH, 0);
            sk_combine<1, false, true><<<cdiv(M*2*HH/2, 256), 256>>>(
                ws, S, b_branch, nullptr, lrf, M, 2*HH, nullptr);
        } else {
            hgemm2<1, false, true><<<dim3(16, gy), 256>>>(
                xhf, Wbrh, Wbrl, b_branch, nullptr, lrf, M, 2*HH, HH+RR, HH, 0, nullptr);
        }

        // child = xc[parent] - selu(lr @ Whid_hi^T + b)  (lo term dropped)
        if (d <= 5) {
            hgemm_sk<1><<<dim3(8, cdiv(M2, 128), S), 256>>>(lrf, Whidh, Whidh, ws, M2, HH, HH, 0, 0);
            sk_combine<2, true, true><<<cdiv(M2*HH/2, 256), 256>>>(
                ws, S, b_hidden, xcB, xcf16, M2, HH, xcA);
        } else {
            hgemm2<2, true, true><<<dim3(8, cdiv(M2, 128)), 256>>>(
                lrf, Whidh, Whidh, b_hidden, xcB, xcf16, M2, HH, HH, 0, 0, xcA);
        }

        float* t; __half* ht;
        t = xcA; xcA = xcB; xcB = t;
        t = hcA; hcA = hcB; hcB = t;
        t = dA;  dA  = dB;  dB  = t;
        ht = hf16A; hf16A = hf16B; hf16B = ht;
    }

    // ---- leaf step (M = 32768): GRU + hb only ----
    {
        int M = MAXM;
        int gy = M / 128;
        hgemm2<0, false, true><<<dim3(6, gy), 256>>>(
            xcf16, Wihf, Wihf, b_ih, nullptr, gif, M, 768, HH, 0, 0, nullptr);
        hgemm2<0, false, true><<<dim3(6, gy), 256>>>(
            hf16A, Whhf, Whhf, b_hh, nullptr, ghf, M, 768, RR, 0, 1, nullptr);
        gru_fused<false, false><<<cdiv(M, 8), 256>>>(
            gif, ghf, hcA, xcA, W_hb, b_hb, dA, dB,
            nullptr, nullptr, nullptr, M, 1);
        out_kernel<<<cdiv(M*(HH+1), 256), 256>>>(xcA, dB, (float*)d_out);
    }
}

// round 15
// speedup vs baseline: 4.9228x; 1.1939x over previous
#include <cuda_runtime.h>
#include <cuda_fp16.h>
#include <math.h>
#include <stdint.h>

// ---------------------------------------------------------------------------
// Problem constants
// ---------------------------------------------------------------------------
#define BB   64
#define SS   32
#define HH   1024
#define RR   256
#define DEPTH 9
#define MAXM (BB*512)
#define OSTR (HH + 1)          // output row stride (1025)

#define SELU_SCALE 1.0507009873554805f
#define SELU_ALPHA 1.6732632423543772f

__device__ __forceinline__ float seluf(float v) {
    return v > 0.f ? SELU_SCALE * v : SELU_SCALE * SELU_ALPHA * expm1f(v);
}
__device__ __forceinline__ float sigmoidf_(float v) {
    return 1.f / (1.f + __expf(-v));
}

// ---------------------------------------------------------------------------
// Scratch (device globals; allocation is forbidden)
// ---------------------------------------------------------------------------
__device__ float g_xcA[(size_t)MAXM * HH];
__device__ float g_xcB[(size_t)MAXM * HH];
__device__ float g_dA[MAXM];
__device__ float g_dB[MAXM];
__device__ float g_y [(size_t)BB * SS * HH];
__device__ float g_ws[(size_t)8388608];          // split-K workspace (32 MB)
__device__ __half g_gif[(size_t)MAXM * 3 * RR];
__device__ __half g_ghf[(size_t)MAXM * 3 * RR];
__device__ __half g_xcf16[(size_t)MAXM * HH];
__device__ __half g_hf16A[(size_t)MAXM * RR];
__device__ __half g_hf16B[(size_t)MAXM * RR];
__device__ __half g_sxf[(size_t)BB * SS * HH];
__device__ __half g_lrf[(size_t)MAXM * HH];      // branch out viewed [2M,1024]
// weights
__device__ __half g_Whidh[HH * HH];
__device__ __half g_Whidl[HH * HH];
__device__ __half g_Wbrh[2 * HH * (HH + RR)];
__device__ __half g_Wbrl[2 * HH * (HH + RR)];
__device__ __half g_Wihf[3 * RR * HH];
__device__ __half g_Whhf[3 * RR * RR];

// ---------------------------------------------------------------------------
// mma.sync helpers
// ---------------------------------------------------------------------------
__device__ __forceinline__ void ldsm4(uint32_t* r, const void* p) {
    uint32_t a = (uint32_t)__cvta_generic_to_shared(p);
    asm volatile("ldmatrix.sync.aligned.m8n8.x4.shared.b16 {%0,%1,%2,%3}, [%4];"
        : "=r"(r[0]), "=r"(r[1]), "=r"(r[2]), "=r"(r[3]) : "r"(a));
}
__device__ __forceinline__ void mma_f16(float* d, const uint32_t* a, uint32_t b0, uint32_t b1) {
    asm volatile("mma.sync.aligned.m16n8k16.row.col.f32.f16.f16.f32 "
        "{%0,%1,%2,%3}, {%4,%5,%6,%7}, {%8,%9}, {%0,%1,%2,%3};"
        : "+f"(d[0]), "+f"(d[1]), "+f"(d[2]), "+f"(d[3])
        : "r"(a[0]), "r"(a[1]), "r"(a[2]), "r"(a[3]), "r"(b0), "r"(b1));
}

// ---------------------------------------------------------------------------
// 2-term fp16 GEMM: C[M,N] = epi( A@Wh^T + A[:, :K2]@Wl[:, :K2]^T + bias )
//   DUALA: logical A row = [xc fp16 (1024, stride HH) | hc fp16 (256, stride RR)]
//   OSTRIDE: fp32 output written at row stride OSTR (into d_out), scalar stores
//   EPI 0: bias   EPI 1: selu   EPI 2: P[r>>1] - selu
// ---------------------------------------------------------------------------
template<int EPI, bool OF32, bool OF16, bool DUALA, bool OSTRIDE>
__global__ __launch_bounds__(256, 2)
void hgemm2(const __half* __restrict__ A, const __half* __restrict__ A2,
            const __half* __restrict__ Wh, const __half* __restrict__ Wl,
            const float* __restrict__ bias,
            float* __restrict__ Cf, __half* __restrict__ Cf16,
            int M, int N, int K, int K2, int ashift, const float* __restrict__ P)
{
    __shared__ __half As[2][128][40];
    __shared__ __half Ws[2][128][40];

    const int tid = threadIdx.x;
    const int warp = tid >> 5, lane = tid & 31;
    const int wm = warp >> 2, wn = warp & 3;
    const int row0 = blockIdx.y * 128, col0 = blockIdx.x * 128;

    const int kt1 = K >> 5;
    const int total = kt1 + (K2 >> 5);

    float acc[4][4][4];
    #pragma unroll
    for (int a = 0; a < 4; a++)
        #pragma unroll
        for (int b = 0; b < 4; b++)
            #pragma unroll
            for (int c = 0; c < 4; c++) acc[a][b][c] = 0.f;

    uint4 ra[2], rw[2];

    auto loadg = [&](int it) {
        int ph = (it >= kt1) ? 1 : 0;
        int k0 = (it - (ph ? kt1 : 0)) << 5;
        const __half* Wp = ph ? Wl : Wh;
        #pragma unroll
        for (int i = 0; i < 2; i++) {
            int u = (i << 8) + tid;
            int r = u >> 2, c = (u & 3) << 3;
            int gr = row0 + r;
            const __half* ap;
            size_t aoff;
            if (DUALA) {
                if (k0 >= HH) { ap = A2; aoff = (size_t)gr * RR + (k0 - HH) + c; }
                else          { ap = A;  aoff = (size_t)gr * HH + k0 + c; }
            } else {
                ap = A; aoff = (size_t)(gr >> ashift) * K + k0 + c;
            }
            ra[i] = (gr < M) ? *(const uint4*)(ap + aoff) : make_uint4(0u, 0u, 0u, 0u);
            rw[i] = *(const uint4*)(Wp + (size_t)(col0 + r) * K + k0 + c);
        }
    };
    auto sts = [&](int buf) {
        #pragma unroll
        for (int i = 0; i < 2; i++) {
            int u = (i << 8) + tid;
            int r = u >> 2, c = (u & 3) << 3;
            *(uint4*)&As[buf][r][c] = ra[i];
            *(uint4*)&Ws[buf][r][c] = rw[i];
        }
    };

    loadg(0);
    sts(0);
    __syncthreads();

    const int a_r = (lane & 15);
    const int a_c = (lane >> 4) << 3;
    const int b_r = (lane & 7) + ((lane >> 4) << 3);
    const int b_c = ((lane >> 3) & 1) << 3;

    for (int it = 0; it < total; ++it) {
        int cur = it & 1;
        bool more = (it + 1 < total);
        if (more) loadg(it + 1);

        #pragma unroll
        for (int s = 0; s < 2; s++) {
            uint32_t afr[4][4], bfr[2][4];
            #pragma unroll
            for (int mt = 0; mt < 4; mt++)
                ldsm4(afr[mt], &As[cur][wm * 64 + mt * 16 + a_r][s * 16 + a_c]);
            #pragma unroll
            for (int p = 0; p < 2; p++)
                ldsm4(bfr[p], &Ws[cur][wn * 32 + p * 16 + b_r][s * 16 + b_c]);
            #pragma unroll
            for (int mt = 0; mt < 4; mt++)
                #pragma unroll
                for (int nt = 0; nt < 4; nt++)
                    mma_f16(acc[mt][nt], afr[mt],
                            bfr[nt >> 1][(nt & 1) * 2], bfr[nt >> 1][(nt & 1) * 2 + 1]);
        }

        if (more) sts(cur ^ 1);
        __syncthreads();
    }

    // ---- epilogue ----
    const int g = lane >> 2, t = lane & 3;
    #pragma unroll
    for (int mt = 0; mt < 4; mt++) {
        #pragma unroll
        for (int half = 0; half < 2; half++) {
            int r = row0 + wm * 64 + mt * 16 + g + half * 8;
            if (r >= M) continue;
            #pragma unroll
            for (int nt = 0; nt < 4; nt++) {
                int c = col0 + wn * 32 + nt * 8 + (t << 1);
                float v0 = acc[mt][nt][half * 2 + 0] + bias[c];
                float v1 = acc[mt][nt][half * 2 + 1] + bias[c + 1];
                if (EPI == 1) { v0 = seluf(v0); v1 = seluf(v1); }
                if (EPI == 2) {
                    float2 p = *(const float2*)(P + (size_t)(r >> 1) * HH + c);
                    v0 = p.x - seluf(v0);
                    v1 = p.y - seluf(v1);
                }
                if (OSTRIDE) {
                    Cf[(size_t)r * OSTR + c]     = v0;
                    Cf[(size_t)r * OSTR + c + 1] = v1;
                } else if (OF32) {
                    *(float2*)(Cf + (size_t)r * N + c) = make_float2(v0, v1);
                }
                if (OF16)
                    *(__half2*)(Cf16 + (size_t)r * N + c) = __floats2half2_rn(v0, v1);
            }
        }
    }
}

// ---------------------------------------------------------------------------
// Split-K GEMM: partial sums to ws[split][M][N], no bias/epilogue.
// ---------------------------------------------------------------------------
template<int TERMS, bool DUALA>
__global__ __launch_bounds__(256, 2)
void hgemm_sk(const __half* __restrict__ A, const __half* __restrict__ A2,
              const __half* __restrict__ Wh, const __half* __restrict__ Wl,
              float* __restrict__ ws,
              int M, int N, int K, int K2, int ashift)
{
    __shared__ __half As[2][128][40];
    __shared__ __half Ws[2][128][40];

    const int tid = threadIdx.x;
    const int warp = tid >> 5, lane = tid & 31;
    const int wm = warp >> 2, wn = warp & 3;
    const int row0 = blockIdx.y * 128, col0 = blockIdx.x * 128;

    const int kt1 = K >> 5;
    const int ktt = (TERMS == 2) ? kt1 + (K2 >> 5) : kt1;
    const int tps = ktt / gridDim.z;
    const int t0 = blockIdx.z * tps, t1 = t0 + tps;

    float acc[4][4][4];
    #pragma unroll
    for (int a = 0; a < 4; a++)
        #pragma unroll
        for (int b = 0; b < 4; b++)
            #pragma unroll
            for (int c = 0; c < 4; c++) acc[a][b][c] = 0.f;

    uint4 ra[2], rw[2];

    auto loadg = [&](int it) {
        int ph = (TERMS == 2 && it >= kt1) ? 1 : 0;
        int k0 = (it - (ph ? kt1 : 0)) << 5;
        const __half* Wp = ph ? Wl : Wh;
        #pragma unroll
        for (int i = 0; i < 2; i++) {
            int u = (i << 8) + tid;
            int r = u >> 2, c = (u & 3) << 3;
            int gr = row0 + r;
            const __half* ap;
            size_t aoff;
            if (DUALA) {
                if (k0 >= HH) { ap = A2; aoff = (size_t)gr * RR + (k0 - HH) + c; }
                else          { ap = A;  aoff = (size_t)gr * HH + k0 + c; }
            } else {
                ap = A; aoff = (size_t)(gr >> ashift) * K + k0 + c;
            }
            ra[i] = (gr < M) ? *(const uint4*)(ap + aoff) : make_uint4(0u, 0u, 0u, 0u);
            rw[i] = *(const uint4*)(Wp + (size_t)(col0 + r) * K + k0 + c);
        }
    };
    auto sts = [&](int buf) {
        #pragma unroll
        for (int i = 0; i < 2; i++) {
            int u = (i << 8) + tid;
            int r = u >> 2, c = (u & 3) << 3;
            *(uint4*)&As[buf][r][c] = ra[i];
            *(uint4*)&Ws[buf][r][c] = rw[i];
        }
    };

    loadg(t0);
    sts(0);
    __syncthreads();

    const int a_r = (lane & 15);
    const int a_c = (lane >> 4) << 3;
    const int b_r = (lane & 7) + ((lane >> 4) << 3);
    const int b_c = ((lane >> 3) & 1) << 3;

    for (int it = t0; it < t1; ++it) {
        int cur = (it - t0) & 1;
        bool more = (it + 1 < t1);
        if (more) loadg(it + 1);

        #pragma unroll
        for (int s = 0; s < 2; s++) {
            uint32_t afr[4][4], bfr[2][4];
            #pragma unroll
            for (int mt = 0; mt < 4; mt++)
                ldsm4(afr[mt], &As[cur][wm * 64 + mt * 16 + a_r][s * 16 + a_c]);
            #pragma unroll
            for (int p = 0; p < 2; p++)
                ldsm4(bfr[p], &Ws[cur][wn * 32 + p * 16 + b_r][s * 16 + b_c]);
            #pragma unroll
            for (int mt = 0; mt < 4; mt++)
                #pragma unroll
                for (int nt = 0; nt < 4; nt++)
                    mma_f16(acc[mt][nt], afr[mt],
                            bfr[nt >> 1][(nt & 1) * 2], bfr[nt >> 1][(nt & 1) * 2 + 1]);
        }

        if (more) sts(cur ^ 1);
        __syncthreads();
    }

    float* wp = ws + (size_t)blockIdx.z * M * N;
    const int g = lane >> 2, t = lane & 3;
    #pragma unroll
    for (int mt = 0; mt < 4; mt++) {
        #pragma unroll
        for (int half = 0; half < 2; half++) {
            int r = row0 + wm * 64 + mt * 16 + g + half * 8;
            if (r >= M) continue;
            #pragma unroll
            for (int nt = 0; nt < 4; nt++) {
                int c = col0 + wn * 32 + nt * 8 + (t << 1);
                *(float2*)(wp + (size_t)r * N + c) =
                    make_float2(acc[mt][nt][half * 2 + 0], acc[mt][nt][half * 2 + 1]);
            }
        }
    }
}

// Combine split-K partials: sum S slices, add bias, apply epilogue.
template<int EPI, bool OF32, bool OF16>
__global__ void sk_combine(const float* __restrict__ ws, int S,
                           const float* __restrict__ bias,
                           float* __restrict__ Cf, __half* __restrict__ Cf16,
                           int M, int N, const float* __restrict__ P)
{
    int i = blockIdx.x * blockDim.x + threadIdx.x;
    if (i >= M * (N >> 1)) return;
    int r = (i << 1) / N, c = (i << 1) % N;
    size_t off = (size_t)r * N + c;
    float2 s = make_float2(0.f, 0.f);
    for (int k = 0; k < S; k++) {
        float2 v = *(const float2*)(ws + (size_t)k * M * N + off);
        s.x += v.x; s.y += v.y;
    }
    float v0 = s.x + bias[c], v1 = s.y + bias[c + 1];
    if (EPI == 1) { v0 = seluf(v0); v1 = seluf(v1); }
    if (EPI == 2) {
        float2 p = *(const float2*)(P + (size_t)(r >> 1) * HH + c);
        v0 = p.x - seluf(v0);
        v1 = p.y - seluf(v1);
    }
    if (OF32) *(float2*)(Cf + off) = make_float2(v0, v1);
    if (OF16) *(__half2*)(Cf16 + off) = __floats2half2_rn(v0, v1);
}

// ---------------------------------------------------------------------------
// Fused GRU + hb + depth. Warp per row, 8 warps/block. All fp16 state.
//   LEAF: depth written to dOut[m*OSTR + 1024] (d_out); no hc out.
// ---------------------------------------------------------------------------
template<bool WRITE_HC, bool LEAF>
__global__ void gru_fused(const __half* __restrict__ gi, const __half* __restrict__ gh,
                          const __half* __restrict__ hPrev, const __half* __restrict__ xc16,
                          const float* __restrict__ Whb, const float* __restrict__ bhb,
                          const float* __restrict__ dPrev, float* __restrict__ dOut,
                          __half* __restrict__ hOut,
                          int M, int shift)
{
    const int m = blockIdx.x * 8 + (threadIdx.x >> 5);
    const int lane = threadIdx.x & 31;
    if (m >= M) return;
    const int p = m >> shift;
    const size_t o = (size_t)m * 768;
    const size_t hp = (size_t)p * RR;
    const size_t hm = (size_t)m * RR;

    float v[8];
    #pragma unroll
    for (int u = 0; u < 8; u++) {
        int j = lane + 32 * u;
        float ir = __half2float(gi[o + j]);
        float iz = __half2float(gi[o + 256 + j]);
        float inn = __half2float(gi[o + 512 + j]);
        float hr = __half2float(gh[o + j]);
        float hz = __half2float(gh[o + 256 + j]);
        float hn = __half2float(gh[o + 512 + j]);
        float r = sigmoidf_(ir + hr);
        float z = sigmoidf_(iz + hz);
        float n = tanhf(inn + r * hn);
        float h = __half2float(hPrev[hp + j]);
        float nv = (1.f - z) * n + z * h;
        v[u] = nv;
        if (WRITE_HC) hOut[hm + j] = __float2half(nv);
    }

    // hb dot over [xc(1024, fp16) | hc_new(256)]
    const uint4* xr = (const uint4*)(xc16 + (size_t)m * HH);
    const float4* w4 = (const float4*)Whb;
    float s = 0.f;
    #pragma unroll
    for (int it = 0; it < 4; it++) {
        int i = lane + 32 * it;               // 8 halves at cols i*8
        uint4 uu = xr[i];
        __half2 p0 = *(__half2*)&uu.x, p1 = *(__half2*)&uu.y;
        __half2 p2 = *(__half2*)&uu.z, p3 = *(__half2*)&uu.w;
        float4 wa = w4[2 * i], wb = w4[2 * i + 1];
        s += __low2float(p0) * wa.x + __high2float(p0) * wa.y
           + __low2float(p1) * wa.z + __high2float(p1) * wa.w;
        s += __low2float(p2) * wb.x + __high2float(p2) * wb.y
           + __low2float(p3) * wb.z + __high2float(p3) * wb.w;
    }
    #pragma unroll
    for (int u = 0; u < 8; u++) {
        int j = lane + 32 * u;
        s += v[u] * Whb[1024 + j];
    }
    #pragma unroll
    for (int off = 16; off; off >>= 1) s += __shfl_xor_sync(0xffffffffu, s, off);
    if (lane == 0) {
        float dv = dPrev[p] + sigmoidf_(s + bhb[0]);
        if (LEAF) dOut[(size_t)m * OSTR + HH] = dv;
        else      dOut[m] = dv;
    }
}

// ---------------------------------------------------------------------------
// Misc elementwise kernels
// ---------------------------------------------------------------------------
__global__ void half_split_kernel(const float* __restrict__ in, __half* __restrict__ h,
                                  __half* __restrict__ l, int n) {
    int i = blockIdx.x * blockDim.x + threadIdx.x;
    if (i < n) {
        __half hv = __float2half(in[i]);
        h[i] = hv;
        l[i] = __float2half(in[i] - __half2float(hv));
    }
}
__global__ void half_cast_kernel(const float* __restrict__ in, __half* __restrict__ out, int n) {
    int i = blockIdx.x * blockDim.x + threadIdx.x;
    if (i < n) out[i] = __float2half(in[i]);
}
__global__ void selu_half_kernel(const float* __restrict__ in, __half* __restrict__ out, int n) {
    int i = blockIdx.x * blockDim.x + threadIdx.x;
    if (i < n) out[i] = __float2half(seluf(in[i]));
}
__global__ void mean_kernel(const float* __restrict__ y, float* __restrict__ xc,
                            __half* __restrict__ xf16) {
    int i = blockIdx.x * blockDim.x + threadIdx.x;
    if (i >= BB * HH) return;
    int b = i >> 10, h = i & (HH - 1);
    float s = 0.f;
    #pragma unroll 8
    for (int t = 0; t < SS; t++) s += y[((size_t)(b * SS + t)) * HH + h];
    float v = s * (1.f / SS);
    xc[i] = v;
    xf16[i] = __float2half(v);
}
__global__ void zero32_kernel(uint32_t* p, int n) {
    int i = blockIdx.x * blockDim.x + threadIdx.x;
    if (i < n) p[i] = 0u;
}

// ---------------------------------------------------------------------------
// Host driver (graph-capturable: only kernel launches)
// ---------------------------------------------------------------------------
static inline int cdiv(int a, int b) { return (a + b - 1) / b; }

extern "C" void kernel_launch(void* const* d_in, const int* in_sizes, int n_in,
                              void* d_out, int out_size)
{
    const float* x        = (const float*)d_in[0];
    const float* W_hidden = (const float*)d_in[1];
    const float* b_hidden = (const float*)d_in[2];
    const float* W_hb     = (const float*)d_in[3];
    const float* b_hb     = (const float*)d_in[4];
    const float* W_branch = (const float*)d_in[5];
    const float* b_branch = (const float*)d_in[6];
    const float* W_ih     = (const float*)d_in[7];
    const float* W_hh     = (const float*)d_in[8];
    const float* b_ih     = (const float*)d_in[9];
    const float* b_hh     = (const float*)d_in[10];

    float *xcA, *xcB, *dA, *dB, *y, *ws;
    __half *gif, *ghf, *xcf16, *hf16A, *hf16B, *sxf, *lrf;
    __half *Whidh, *Whidl, *Wbrh, *Wbrl, *Wihf, *Whhf;

    cudaGetSymbolAddress((void**)&xcA, g_xcA);   cudaGetSymbolAddress((void**)&xcB, g_xcB);
    cudaGetSymbolAddress((void**)&dA,  g_dA);    cudaGetSymbolAddress((void**)&dB,  g_dB);
    cudaGetSymbolAddress((void**)&y,   g_y);     cudaGetSymbolAddress((void**)&ws,  g_ws);
    cudaGetSymbolAddress((void**)&gif, g_gif);   cudaGetSymbolAddress((void**)&ghf, g_ghf);
    cudaGetSymbolAddress((void**)&xcf16, g_xcf16);
    cudaGetSymbolAddress((void**)&hf16A, g_hf16A); cudaGetSymbolAddress((void**)&hf16B, g_hf16B);
    cudaGetSymbolAddress((void**)&sxf, g_sxf);
    cudaGetSymbolAddress((void**)&lrf, g_lrf);
    cudaGetSymbolAddress((void**)&Whidh, g_Whidh); cudaGetSymbolAddress((void**)&Whidl, g_Whidl);
    cudaGetSymbolAddress((void**)&Wbrh, g_Wbrh);   cudaGetSymbolAddress((void**)&Wbrl, g_Wbrl);
    cudaGetSymbolAddress((void**)&Wihf, g_Wihf);   cudaGetSymbolAddress((void**)&Whhf, g_Whhf);

    const int nsx = BB * SS * HH;

    // ---- weight prep ----
    half_split_kernel<<<cdiv(HH*HH, 256), 256>>>(W_hidden, Whidh, Whidl, HH*HH);
    half_split_kernel<<<cdiv(2*HH*(HH+RR), 256), 256>>>(W_branch, Wbrh, Wbrl, 2*HH*(HH+RR));
    half_cast_kernel<<<cdiv(3*RR*HH, 256), 256>>>(W_ih, Wihf, 3*RR*HH);
    half_cast_kernel<<<cdiv(3*RR*RR, 256), 256>>>(W_hh, Whhf, 3*RR*RR);

    // ---- root: xc0 = mean_s selu(selu(x) @ W_hidden^T + b_hidden) ----
    selu_half_kernel<<<cdiv(nsx, 256), 256>>>(x, sxf, nsx);
    hgemm2<1, true, false, false, false><<<dim3(HH/128, (BB*SS)/128), 256>>>(
        sxf, sxf, Whidh, Whidl, b_hidden, y, nullptr, BB*SS, HH, HH, HH, 0, nullptr);
    mean_kernel<<<cdiv(BB*HH, 256), 256>>>(y, xcA, xcf16);

    zero32_kernel<<<cdiv(BB*RR/2, 256), 256>>>((uint32_t*)hf16A, BB*RR/2);
    zero32_kernel<<<1, 64>>>((uint32_t*)dA, BB);

    // ---- levels 0 .. DEPTH-1 ----
    for (int d = 0; d < DEPTH; d++) {
        int M  = BB << d;
        int M2 = M << 1;
        int gy = cdiv(M, 128);
        int shift = (d == 0) ? 0 : 1;
        int S = (d <= 3) ? 8 : ((d == 4) ? 4 : 2);

        // gi = xc @ W_ih^T -> fp16
        if (d <= 6) {
            hgemm_sk<1, false><<<dim3(6, gy, S), 256>>>(
                xcf16, xcf16, Wihf, Wihf, ws, M, 768, HH, 0, 0);
            sk_combine<0, false, true><<<cdiv(M*768/2, 256), 256>>>(
                ws, S, b_ih, nullptr, gif, M, 768, nullptr);
        } else {
            hgemm2<0, false, true, false, false><<<dim3(6, gy), 256>>>(
                xcf16, xcf16, Wihf, Wihf, b_ih, nullptr, gif, M, 768, HH, 0, 0, nullptr);
        }

        // gh = hc[parent] @ W_hh^T -> fp16
        hgemm2<0, false, true, false, false><<<dim3(6, gy), 256>>>(
            hf16A, hf16A, Whhf, Whhf, b_hh, nullptr, ghf, M, 768, RR, 0, shift, nullptr);

        // GRU + hb + depth (fp16 state; no xh materialization)
        gru_fused<true, false><<<cdiv(M, 8), 256>>>(
            gif, ghf, hf16A, xcf16, W_hb, b_hb, dA, dB, hf16B, M, shift);

        // branch = selu([xc|hc] @ Wbrh^T + xc @ Wbrl[:, :1024]^T + b) -> fp16 lr
        // lo term kept at d<=6, dropped at d=7,8
        if (d <= 5) {
            hgemm_sk<2, true><<<dim3(16, gy, S), 256>>>(
                xcf16, hf16B, Wbrh, Wbrl, ws, M, 2*HH, HH+RR, HH, 0);
            sk_combine<1, false, true><<<cdiv(M*2*HH/2, 256), 256>>>(
                ws, S, b_branch, nullptr, lrf, M, 2*HH, nullptr);
        } else {
            int K2b = (d == 6) ? HH : 0;
            hgemm2<1, false, true, true, false><<<dim3(16, gy), 256>>>(
                xcf16, hf16B, Wbrh, Wbrl, b_branch, nullptr, lrf,
                M, 2*HH, HH+RR, K2b, 0, nullptr);
        }

        // child = xc[parent] - selu(lr @ Whid_hi^T + b)
        if (d <= 5) {
            hgemm_sk<1, false><<<dim3(8, cdiv(M2, 128), S), 256>>>(
                lrf, lrf, Whidh, Whidh, ws, M2, HH, HH, 0, 0);
            sk_combine<2, true, true><<<cdiv(M2*HH/2, 256), 256>>>(
                ws, S, b_hidden, xcB, xcf16, M2, HH, xcA);
        } else if (d <= 7) {
            hgemm2<2, true, true, false, false><<<dim3(8, cdiv(M2, 128)), 256>>>(
                lrf, lrf, Whidh, Whidh, b_hidden, xcB, xcf16, M2, HH, HH, 0, 0, xcA);
        } else {
            // d = 8: final xc goes straight into d_out (stride 1025) + fp16
            hgemm2<2, false, true, false, true><<<dim3(8, M2/128), 256>>>(
                lrf, lrf, Whidh, Whidh, b_hidden, (float*)d_out, xcf16,
                M2, HH, HH, 0, 0, xcA);
        }

        float* t; __half* ht;
        t = xcA; xcA = xcB; xcB = t;
        t = dA;  dA  = dB;  dB  = t;
        ht = hf16A; hf16A = hf16B; hf16B = ht;
    }

    // ---- leaf step (M = 32768): GRU gates + depth into d_out ----
    {
        int M = MAXM;
        int gy = M / 128;
        hgemm2<0, false, true, false, false><<<dim3(6, gy), 256>>>(
            xcf16, xcf16, Wihf, Wihf, b_ih, nullptr, gif, M, 768, HH, 0, 0, nullptr);
        hgemm2<0, false, true, false, false><<<dim3(6, gy), 256>>>(
            hf16A, hf16A, Whhf, Whhf, b_hh, nullptr, ghf, M, 768, RR, 0, 1, nullptr);
        gru_fused<false, true><<<cdiv(M, 8), 256>>>(
            gif, ghf, hf16A, xcf16, W_hb, b_hb, dA, (float*)d_out, nullptr, M, 1);
    }
}

// round 16
// speedup vs baseline: 5.1691x; 1.0500x over previous
#include <cuda_runtime.h>
#include <cuda_fp16.h>
#include <math.h>
#include <stdint.h>

// ---------------------------------------------------------------------------
// Problem constants
// ---------------------------------------------------------------------------
#define BB   64
#define SS   32
#define HH   1024
#define RR   256
#define DEPTH 9
#define MAXM (BB*512)
#define OSTR (HH + 1)          // output row stride (1025)

#define SELU_SCALE 1.0507009873554805f
#define SELU_ALPHA 1.6732632423543772f

__device__ __forceinline__ float seluf(float v) {
    return v > 0.f ? SELU_SCALE * v : SELU_SCALE * SELU_ALPHA * expm1f(v);
}
__device__ __forceinline__ float sigmoidf_(float v) {
    return 1.f / (1.f + __expf(-v));
}

// ---------------------------------------------------------------------------
// Scratch (device globals; allocation is forbidden)
// ---------------------------------------------------------------------------
__device__ float g_xcA[(size_t)MAXM * HH];
__device__ float g_xcB[(size_t)MAXM * HH];
__device__ float g_dA[MAXM];
__device__ float g_dB[MAXM];
__device__ float g_y [(size_t)BB * SS * HH];
__device__ float g_ws[(size_t)8388608];          // split-K workspace (32 MB)
__device__ __half g_gif[(size_t)MAXM * 3 * RR];
__device__ __half g_ghf[(size_t)(MAXM/2) * 3 * RR];   // parent-resolution gates
__device__ __half g_xcf16[(size_t)MAXM * HH];
__device__ __half g_hf16A[(size_t)MAXM * RR];
__device__ __half g_hf16B[(size_t)MAXM * RR];
__device__ __half g_sxf[(size_t)BB * SS * HH];
__device__ __half g_lrf[(size_t)MAXM * HH];      // branch out viewed [2M,1024]
// weights
__device__ __half g_Whidh[HH * HH];
__device__ __half g_Whidl[HH * HH];
__device__ __half g_Wbrh[2 * HH * (HH + RR)];
__device__ __half g_Wbrl[2 * HH * (HH + RR)];
__device__ __half g_Wihf[3 * RR * HH];
__device__ __half g_Whhf[3 * RR * RR];

// ---------------------------------------------------------------------------
// mma.sync helpers
// ---------------------------------------------------------------------------
__device__ __forceinline__ void ldsm4(uint32_t* r, const void* p) {
    uint32_t a = (uint32_t)__cvta_generic_to_shared(p);
    asm volatile("ldmatrix.sync.aligned.m8n8.x4.shared.b16 {%0,%1,%2,%3}, [%4];"
        : "=r"(r[0]), "=r"(r[1]), "=r"(r[2]), "=r"(r[3]) : "r"(a));
}
__device__ __forceinline__ void mma_f16(float* d, const uint32_t* a, uint32_t b0, uint32_t b1) {
    asm volatile("mma.sync.aligned.m16n8k16.row.col.f32.f16.f16.f32 "
        "{%0,%1,%2,%3}, {%4,%5,%6,%7}, {%8,%9}, {%0,%1,%2,%3};"
        : "+f"(d[0]), "+f"(d[1]), "+f"(d[2]), "+f"(d[3])
        : "r"(a[0]), "r"(a[1]), "r"(a[2]), "r"(a[3]), "r"(b0), "r"(b1));
}

// ---------------------------------------------------------------------------
// 2-term fp16 GEMM: C[M,N] = epi( A@Wh^T + A[:, :K2]@Wl[:, :K2]^T + bias )
//   DUALA: logical A row = [xc fp16 (1024, stride HH) | hc fp16 (256, stride RR)]
//   OSTRIDE: fp32 output written at row stride OSTR (into d_out), scalar stores
//   EPI 0: bias   EPI 1: selu   EPI 2: P[r>>1] - selu
// ---------------------------------------------------------------------------
template<int EPI, bool OF32, bool OF16, bool DUALA, bool OSTRIDE>
__global__ __launch_bounds__(256, 2)
void hgemm2(const __half* __restrict__ A, const __half* __restrict__ A2,
            const __half* __restrict__ Wh, const __half* __restrict__ Wl,
            const float* __restrict__ bias,
            float* __restrict__ Cf, __half* __restrict__ Cf16,
            int M, int N, int K, int K2, int ashift, const float* __restrict__ P)
{
    __shared__ __half As[2][128][40];
    __shared__ __half Ws[2][128][40];

    const int tid = threadIdx.x;
    const int warp = tid >> 5, lane = tid & 31;
    const int wm = warp >> 2, wn = warp & 3;
    const int row0 = blockIdx.y * 128, col0 = blockIdx.x * 128;

    const int kt1 = K >> 5;
    const int total = kt1 + (K2 >> 5);

    float acc[4][4][4];
    #pragma unroll
    for (int a = 0; a < 4; a++)
        #pragma unroll
        for (int b = 0; b < 4; b++)
            #pragma unroll
            for (int c = 0; c < 4; c++) acc[a][b][c] = 0.f;

    uint4 ra[2], rw[2];

    auto loadg = [&](int it) {
        int ph = (it >= kt1) ? 1 : 0;
        int k0 = (it - (ph ? kt1 : 0)) << 5;
        const __half* Wp = ph ? Wl : Wh;
        #pragma unroll
        for (int i = 0; i < 2; i++) {
            int u = (i << 8) + tid;
            int r = u >> 2, c = (u & 3) << 3;
            int gr = row0 + r;
            const __half* ap;
            size_t aoff;
            if (DUALA) {
                if (k0 >= HH) { ap = A2; aoff = (size_t)gr * RR + (k0 - HH) + c; }
                else          { ap = A;  aoff = (size_t)gr * HH + k0 + c; }
            } else {
                ap = A; aoff = (size_t)(gr >> ashift) * K + k0 + c;
            }
            ra[i] = (gr < M) ? *(const uint4*)(ap + aoff) : make_uint4(0u, 0u, 0u, 0u);
            rw[i] = *(const uint4*)(Wp + (size_t)(col0 + r) * K + k0 + c);
        }
    };
    auto sts = [&](int buf) {
        #pragma unroll
        for (int i = 0; i < 2; i++) {
            int u = (i << 8) + tid;
            int r = u >> 2, c = (u & 3) << 3;
            *(uint4*)&As[buf][r][c] = ra[i];
            *(uint4*)&Ws[buf][r][c] = rw[i];
        }
    };

    loadg(0);
    sts(0);
    __syncthreads();

    const int a_r = (lane & 15);
    const int a_c = (lane >> 4) << 3;
    const int b_r = (lane & 7) + ((lane >> 4) << 3);
    const int b_c = ((lane >> 3) & 1) << 3;

    for (int it = 0; it < total; ++it) {
        int cur = it & 1;
        bool more = (it + 1 < total);
        if (more) loadg(it + 1);

        #pragma unroll
        for (int s = 0; s < 2; s++) {
            uint32_t afr[4][4], bfr[2][4];
            #pragma unroll
            for (int mt = 0; mt < 4; mt++)
                ldsm4(afr[mt], &As[cur][wm * 64 + mt * 16 + a_r][s * 16 + a_c]);
            #pragma unroll
            for (int p = 0; p < 2; p++)
                ldsm4(bfr[p], &Ws[cur][wn * 32 + p * 16 + b_r][s * 16 + b_c]);
            #pragma unroll
            for (int mt = 0; mt < 4; mt++)
                #pragma unroll
                for (int nt = 0; nt < 4; nt++)
                    mma_f16(acc[mt][nt], afr[mt],
                            bfr[nt >> 1][(nt & 1) * 2], bfr[nt >> 1][(nt & 1) * 2 + 1]);
        }

        if (more) sts(cur ^ 1);
        __syncthreads();
    }

    // ---- epilogue ----
    const int g = lane >> 2, t = lane & 3;
    #pragma unroll
    for (int mt = 0; mt < 4; mt++) {
        #pragma unroll
        for (int half = 0; half < 2; half++) {
            int r = row0 + wm * 64 + mt * 16 + g + half * 8;
            if (r >= M) continue;
            #pragma unroll
            for (int nt = 0; nt < 4; nt++) {
                int c = col0 + wn * 32 + nt * 8 + (t << 1);
                float v0 = acc[mt][nt][half * 2 + 0] + bias[c];
                float v1 = acc[mt][nt][half * 2 + 1] + bias[c + 1];
                if (EPI == 1) { v0 = seluf(v0); v1 = seluf(v1); }
                if (EPI == 2) {
                    float2 p = *(const float2*)(P + (size_t)(r >> 1) * HH + c);
                    v0 = p.x - seluf(v0);
                    v1 = p.y - seluf(v1);
                }
                if (OSTRIDE) {
                    Cf[(size_t)r * OSTR + c]     = v0;
                    Cf[(size_t)r * OSTR + c + 1] = v1;
                } else if (OF32) {
                    *(float2*)(Cf + (size_t)r * N + c) = make_float2(v0, v1);
                }
                if (OF16)
                    *(__half2*)(Cf16 + (size_t)r * N + c) = __floats2half2_rn(v0, v1);
            }
        }
    }
}

// ---------------------------------------------------------------------------
// Split-K GEMM: partial sums to ws[split][M][N], no bias/epilogue.
// ---------------------------------------------------------------------------
template<int TERMS, bool DUALA>
__global__ __launch_bounds__(256, 2)
void hgemm_sk(const __half* __restrict__ A, const __half* __restrict__ A2,
              const __half* __restrict__ Wh, const __half* __restrict__ Wl,
              float* __restrict__ ws,
              int M, int N, int K, int K2, int ashift)
{
    __shared__ __half As[2][128][40];
    __shared__ __half Ws[2][128][40];

    const int tid = threadIdx.x;
    const int warp = tid >> 5, lane = tid & 31;
    const int wm = warp >> 2, wn = warp & 3;
    const int row0 = blockIdx.y * 128, col0 = blockIdx.x * 128;

    const int kt1 = K >> 5;
    const int ktt = (TERMS == 2) ? kt1 + (K2 >> 5) : kt1;
    const int tps = ktt / gridDim.z;
    const int t0 = blockIdx.z * tps, t1 = t0 + tps;

    float acc[4][4][4];
    #pragma unroll
    for (int a = 0; a < 4; a++)
        #pragma unroll
        for (int b = 0; b < 4; b++)
            #pragma unroll
            for (int c = 0; c < 4; c++) acc[a][b][c] = 0.f;

    uint4 ra[2], rw[2];

    auto loadg = [&](int it) {
        int ph = (TERMS == 2 && it >= kt1) ? 1 : 0;
        int k0 = (it - (ph ? kt1 : 0)) << 5;
        const __half* Wp = ph ? Wl : Wh;
        #pragma unroll
        for (int i = 0; i < 2; i++) {
            int u = (i << 8) + tid;
            int r = u >> 2, c = (u & 3) << 3;
            int gr = row0 + r;
            const __half* ap;
            size_t aoff;
            if (DUALA) {
                if (k0 >= HH) { ap = A2; aoff = (size_t)gr * RR + (k0 - HH) + c; }
                else          { ap = A;  aoff = (size_t)gr * HH + k0 + c; }
            } else {
                ap = A; aoff = (size_t)(gr >> ashift) * K + k0 + c;
            }
            ra[i] = (gr < M) ? *(const uint4*)(ap + aoff) : make_uint4(0u, 0u, 0u, 0u);
            rw[i] = *(const uint4*)(Wp + (size_t)(col0 + r) * K + k0 + c);
        }
    };
    auto sts = [&](int buf) {
        #pragma unroll
        for (int i = 0; i < 2; i++) {
            int u = (i << 8) + tid;
            int r = u >> 2, c = (u & 3) << 3;
            *(uint4*)&As[buf][r][c] = ra[i];
            *(uint4*)&Ws[buf][r][c] = rw[i];
        }
    };

    loadg(t0);
    sts(0);
    __syncthreads();

    const int a_r = (lane & 15);
    const int a_c = (lane >> 4) << 3;
    const int b_r = (lane & 7) + ((lane >> 4) << 3);
    const int b_c = ((lane >> 3) & 1) << 3;

    for (int it = t0; it < t1; ++it) {
        int cur = (it - t0) & 1;
        bool more = (it + 1 < t1);
        if (more) loadg(it + 1);

        #pragma unroll
        for (int s = 0; s < 2; s++) {
            uint32_t afr[4][4], bfr[2][4];
            #pragma unroll
            for (int mt = 0; mt < 4; mt++)
                ldsm4(afr[mt], &As[cur][wm * 64 + mt * 16 + a_r][s * 16 + a_c]);
            #pragma unroll
            for (int p = 0; p < 2; p++)
                ldsm4(bfr[p], &Ws[cur][wn * 32 + p * 16 + b_r][s * 16 + b_c]);
            #pragma unroll
            for (int mt = 0; mt < 4; mt++)
                #pragma unroll
                for (int nt = 0; nt < 4; nt++)
                    mma_f16(acc[mt][nt], afr[mt],
                            bfr[nt >> 1][(nt & 1) * 2], bfr[nt >> 1][(nt & 1) * 2 + 1]);
        }

        if (more) sts(cur ^ 1);
        __syncthreads();
    }

    float* wp = ws + (size_t)blockIdx.z * M * N;
    const int g = lane >> 2, t = lane & 3;
    #pragma unroll
    for (int mt = 0; mt < 4; mt++) {
        #pragma unroll
        for (int half = 0; half < 2; half++) {
            int r = row0 + wm * 64 + mt * 16 + g + half * 8;
            if (r >= M) continue;
            #pragma unroll
            for (int nt = 0; nt < 4; nt++) {
                int c = col0 + wn * 32 + nt * 8 + (t << 1);
                *(float2*)(wp + (size_t)r * N + c) =
                    make_float2(acc[mt][nt][half * 2 + 0], acc[mt][nt][half * 2 + 1]);
            }
        }
    }
}

// Combine split-K partials: sum S slices, add bias, apply epilogue.
template<int EPI, bool OF32, bool OF16>
__global__ void sk_combine(const float* __restrict__ ws, int S,
                           const float* __restrict__ bias,
                           float* __restrict__ Cf, __half* __restrict__ Cf16,
                           int M, int N, const float* __restrict__ P)
{
    int i = blockIdx.x * blockDim.x + threadIdx.x;
    if (i >= M * (N >> 1)) return;
    int r = (i << 1) / N, c = (i << 1) % N;
    size_t off = (size_t)r * N + c;
    float2 s = make_float2(0.f, 0.f);
    for (int k = 0; k < S; k++) {
        float2 v = *(const float2*)(ws + (size_t)k * M * N + off);
        s.x += v.x; s.y += v.y;
    }
    float v0 = s.x + bias[c], v1 = s.y + bias[c + 1];
    if (EPI == 1) { v0 = seluf(v0); v1 = seluf(v1); }
    if (EPI == 2) {
        float2 p = *(const float2*)(P + (size_t)(r >> 1) * HH + c);
        v0 = p.x - seluf(v0);
        v1 = p.y - seluf(v1);
    }
    if (OF32) *(float2*)(Cf + off) = make_float2(v0, v1);
    if (OF16) *(__half2*)(Cf16 + off) = __floats2half2_rn(v0, v1);
}

// ---------------------------------------------------------------------------
// Fused GRU + hb + depth. Warp per row, 8 warps/block. All fp16 state.
//   gh is PARENT-RESOLUTION: read at row (m >> shift).
//   LEAF: depth written to dOut[m*OSTR + 1024] (d_out); no hc out.
// ---------------------------------------------------------------------------
template<bool WRITE_HC, bool LEAF>
__global__ void gru_fused(const __half* __restrict__ gi, const __half* __restrict__ gh,
                          const __half* __restrict__ hPrev, const __half* __restrict__ xc16,
                          const float* __restrict__ Whb, const float* __restrict__ bhb,
                          const float* __restrict__ dPrev, float* __restrict__ dOut,
                          __half* __restrict__ hOut,
                          int M, int shift)
{
    const int m = blockIdx.x * 8 + (threadIdx.x >> 5);
    const int lane = threadIdx.x & 31;
    if (m >= M) return;
    const int p = m >> shift;
    const size_t o  = (size_t)m * 768;
    const size_t og = (size_t)p * 768;        // parent-resolution gh
    const size_t hp = (size_t)p * RR;
    const size_t hm = (size_t)m * RR;

    float v[8];
    #pragma unroll
    for (int u = 0; u < 8; u++) {
        int j = lane + 32 * u;
        float ir = __half2float(gi[o + j]);
        float iz = __half2float(gi[o + 256 + j]);
        float inn = __half2float(gi[o + 512 + j]);
        float hr = __half2float(gh[og + j]);
        float hz = __half2float(gh[og + 256 + j]);
        float hn = __half2float(gh[og + 512 + j]);
        float r = sigmoidf_(ir + hr);
        float z = sigmoidf_(iz + hz);
        float n = tanhf(inn + r * hn);
        float h = __half2float(hPrev[hp + j]);
        float nv = (1.f - z) * n + z * h;
        v[u] = nv;
        if (WRITE_HC) hOut[hm + j] = __float2half(nv);
    }

    // hb dot over [xc(1024, fp16) | hc_new(256)]
    const uint4* xr = (const uint4*)(xc16 + (size_t)m * HH);
    const float4* w4 = (const float4*)Whb;
    float s = 0.f;
    #pragma unroll
    for (int it = 0; it < 4; it++) {
        int i = lane + 32 * it;
        uint4 uu = xr[i];
        __half2 p0 = *(__half2*)&uu.x, p1 = *(__half2*)&uu.y;
        __half2 p2 = *(__half2*)&uu.z, p3 = *(__half2*)&uu.w;
        float4 wa = w4[2 * i], wb = w4[2 * i + 1];
        s += __low2float(p0) * wa.x + __high2float(p0) * wa.y
           + __low2float(p1) * wa.z + __high2float(p1) * wa.w;
        s += __low2float(p2) * wb.x + __high2float(p2) * wb.y
           + __low2float(p3) * wb.z + __high2float(p3) * wb.w;
    }
    #pragma unroll
    for (int u = 0; u < 8; u++) {
        int j = lane + 32 * u;
        s += v[u] * Whb[1024 + j];
    }
    #pragma unroll
    for (int off = 16; off; off >>= 1) s += __shfl_xor_sync(0xffffffffu, s, off);
    if (lane == 0) {
        float dv = dPrev[p] + sigmoidf_(s + bhb[0]);
        if (LEAF) dOut[(size_t)m * OSTR + HH] = dv;
        else      dOut[m] = dv;
    }
}

// ---------------------------------------------------------------------------
// Misc elementwise kernels
// ---------------------------------------------------------------------------
__global__ void half_split_kernel(const float* __restrict__ in, __half* __restrict__ h,
                                  __half* __restrict__ l, int n) {
    int i = blockIdx.x * blockDim.x + threadIdx.x;
    if (i < n) {
        __half hv = __float2half(in[i]);
        h[i] = hv;
        l[i] = __float2half(in[i] - __half2float(hv));
    }
}
__global__ void half_cast_kernel(const float* __restrict__ in, __half* __restrict__ out, int n) {
    int i = blockIdx.x * blockDim.x + threadIdx.x;
    if (i < n) out[i] = __float2half(in[i]);
}
__global__ void selu_half_kernel(const float* __restrict__ in, __half* __restrict__ out, int n) {
    int i = blockIdx.x * blockDim.x + threadIdx.x;
    if (i < n) out[i] = __float2half(seluf(in[i]));
}
__global__ void mean_kernel(const float* __restrict__ y, float* __restrict__ xc,
                            __half* __restrict__ xf16) {
    int i = blockIdx.x * blockDim.x + threadIdx.x;
    if (i >= BB * HH) return;
    int b = i >> 10, h = i & (HH - 1);
    float s = 0.f;
    #pragma unroll 8
    for (int t = 0; t < SS; t++) s += y[((size_t)(b * SS + t)) * HH + h];
    float v = s * (1.f / SS);
    xc[i] = v;
    xf16[i] = __float2half(v);
}
__global__ void zero32_kernel(uint32_t* p, int n) {
    int i = blockIdx.x * blockDim.x + threadIdx.x;
    if (i < n) p[i] = 0u;
}

// ---------------------------------------------------------------------------
// Host driver (graph-capturable: only kernel launches)
// ---------------------------------------------------------------------------
static inline int cdiv(int a, int b) { return (a + b - 1) / b; }

extern "C" void kernel_launch(void* const* d_in, const int* in_sizes, int n_in,
                              void* d_out, int out_size)
{
    const float* x        = (const float*)d_in[0];
    const float* W_hidden = (const float*)d_in[1];
    const float* b_hidden = (const float*)d_in[2];
    const float* W_hb     = (const float*)d_in[3];
    const float* b_hb     = (const float*)d_in[4];
    const float* W_branch = (const float*)d_in[5];
    const float* b_branch = (const float*)d_in[6];
    const float* W_ih     = (const float*)d_in[7];
    const float* W_hh     = (const float*)d_in[8];
    const float* b_ih     = (const float*)d_in[9];
    const float* b_hh     = (const float*)d_in[10];

    float *xcA, *xcB, *dA, *dB, *y, *ws;
    __half *gif, *ghf, *xcf16, *hf16A, *hf16B, *sxf, *lrf;
    __half *Whidh, *Whidl, *Wbrh, *Wbrl, *Wihf, *Whhf;

    cudaGetSymbolAddress((void**)&xcA, g_xcA);   cudaGetSymbolAddress((void**)&xcB, g_xcB);
    cudaGetSymbolAddress((void**)&dA,  g_dA);    cudaGetSymbolAddress((void**)&dB,  g_dB);
    cudaGetSymbolAddress((void**)&y,   g_y);     cudaGetSymbolAddress((void**)&ws,  g_ws);
    cudaGetSymbolAddress((void**)&gif, g_gif);   cudaGetSymbolAddress((void**)&ghf, g_ghf);
    cudaGetSymbolAddress((void**)&xcf16, g_xcf16);
    cudaGetSymbolAddress((void**)&hf16A, g_hf16A); cudaGetSymbolAddress((void**)&hf16B, g_hf16B);
    cudaGetSymbolAddress((void**)&sxf, g_sxf);
    cudaGetSymbolAddress((void**)&lrf, g_lrf);
    cudaGetSymbolAddress((void**)&Whidh, g_Whidh); cudaGetSymbolAddress((void**)&Whidl, g_Whidl);
    cudaGetSymbolAddress((void**)&Wbrh, g_Wbrh);   cudaGetSymbolAddress((void**)&Wbrl, g_Wbrl);
    cudaGetSymbolAddress((void**)&Wihf, g_Wihf);   cudaGetSymbolAddress((void**)&Whhf, g_Whhf);

    const int nsx = BB * SS * HH;

    // ---- weight prep ----
    half_split_kernel<<<cdiv(HH*HH, 256), 256>>>(W_hidden, Whidh, Whidl, HH*HH);
    half_split_kernel<<<cdiv(2*HH*(HH+RR), 256), 256>>>(W_branch, Wbrh, Wbrl, 2*HH*(HH+RR));
    half_cast_kernel<<<cdiv(3*RR*HH, 256), 256>>>(W_ih, Wihf, 3*RR*HH);
    half_cast_kernel<<<cdiv(3*RR*RR, 256), 256>>>(W_hh, Whhf, 3*RR*RR);

    // ---- root: xc0 = mean_s selu(selu(x) @ W_hidden^T + b_hidden) ----
    selu_half_kernel<<<cdiv(nsx, 256), 256>>>(x, sxf, nsx);
    hgemm2<1, true, false, false, false><<<dim3(HH/128, (BB*SS)/128), 256>>>(
        sxf, sxf, Whidh, Whidl, b_hidden, y, nullptr, BB*SS, HH, HH, HH, 0, nullptr);
    mean_kernel<<<cdiv(BB*HH, 256), 256>>>(y, xcA, xcf16);

    zero32_kernel<<<cdiv(BB*RR/2, 256), 256>>>((uint32_t*)hf16A, BB*RR/2);
    zero32_kernel<<<1, 64>>>((uint32_t*)dA, BB);

    // ---- levels 0 .. DEPTH-1 ----
    for (int d = 0; d < DEPTH; d++) {
        int M  = BB << d;
        int M2 = M << 1;
        int gy = cdiv(M, 128);
        int shift = (d == 0) ? 0 : 1;
        int Mp = M >> shift;                 // distinct gh rows (parent count)
        int S = (d <= 3) ? 8 : ((d == 4) ? 4 : 2);

        // gi = xc @ W_ih^T -> fp16
        if (d <= 6) {
            hgemm_sk<1, false><<<dim3(6, gy, S), 256>>>(
                xcf16, xcf16, Wihf, Wihf, ws, M, 768, HH, 0, 0);
            sk_combine<0, false, true><<<cdiv(M*768/2, 256), 256>>>(
                ws, S, b_ih, nullptr, gif, M, 768, nullptr);
        } else {
            hgemm2<0, false, true, false, false><<<dim3(6, gy), 256>>>(
                xcf16, xcf16, Wihf, Wihf, b_ih, nullptr, gif, M, 768, HH, 0, 0, nullptr);
        }

        // gh = hc @ W_hh^T at PARENT resolution (rows shared by sibling pairs)
        hgemm2<0, false, true, false, false><<<dim3(6, cdiv(Mp, 128)), 256>>>(
            hf16A, hf16A, Whhf, Whhf, b_hh, nullptr, ghf, Mp, 768, RR, 0, 0, nullptr);

        // GRU + hb + depth (fp16 state; gh indexed by parent)
        gru_fused<true, false><<<cdiv(M, 8), 256>>>(
            gif, ghf, hf16A, xcf16, W_hb, b_hb, dA, dB, hf16B, M, shift);

        // branch = selu([xc|hc] @ Wbrh^T + xc @ Wbrl[:, :1024]^T + b) -> fp16 lr
        // lo term kept at d<=5 (split-K), dropped at d>=6
        if (d <= 5) {
            hgemm_sk<2, true><<<dim3(16, gy, S), 256>>>(
                xcf16, hf16B, Wbrh, Wbrl, ws, M, 2*HH, HH+RR, HH, 0);
            sk_combine<1, false, true><<<cdiv(M*2*HH/2, 256), 256>>>(
                ws, S, b_branch, nullptr, lrf, M, 2*HH, nullptr);
        } else {
            hgemm2<1, false, true, true, false><<<dim3(16, gy), 256>>>(
                xcf16, hf16B, Wbrh, Wbrl, b_branch, nullptr, lrf,
                M, 2*HH, HH+RR, 0, 0, nullptr);
        }

        // child = xc[parent] - selu(lr @ Whid_hi^T + b)
        if (d <= 5) {
            hgemm_sk<1, false><<<dim3(8, cdiv(M2, 128), S), 256>>>(
                lrf, lrf, Whidh, Whidh, ws, M2, HH, HH, 0, 0);
            sk_combine<2, true, true><<<cdiv(M2*HH/2, 256), 256>>>(
                ws, S, b_hidden, xcB, xcf16, M2, HH, xcA);
        } else if (d <= 7) {
            hgemm2<2, true, true, false, false><<<dim3(8, cdiv(M2, 128)), 256>>>(
                lrf, lrf, Whidh, Whidh, b_hidden, xcB, xcf16, M2, HH, HH, 0, 0, xcA);
        } else {
            // d = 8: final xc goes straight into d_out (stride 1025) + fp16
            hgemm2<2, false, true, false, true><<<dim3(8, M2/128), 256>>>(
                lrf, lrf, Whidh, Whidh, b_hidden, (float*)d_out, xcf16,
                M2, HH, HH, 0, 0, xcA);
        }

        float* t; __half* ht;
        t = xcA; xcA = xcB; xcB = t;
        t = dA;  dA  = dB;  dB  = t;
        ht = hf16A; hf16A = hf16B; hf16B = ht;
    }

    // ---- leaf step (M = 32768): GRU gates + depth into d_out ----
    {
        int M = MAXM;
        int Mp = M >> 1;                      // 16384 distinct gh rows
        int gy = M / 128;
        hgemm2<0, false, true, false, false><<<dim3(6, gy), 256>>>(
            xcf16, xcf16, Wihf, Wihf, b_ih, nullptr, gif, M, 768, HH, 0, 0, nullptr);
        hgemm2<0, false, true, false, false><<<dim3(6, Mp/128), 256>>>(
            hf16A, hf16A, Whhf, Whhf, b_hh, nullptr, ghf, Mp, 768, RR, 0, 0, nullptr);
        gru_fused<false, true><<<cdiv(M, 8), 256>>>(
            gif, ghf, hf16A, xcf16, W_hb, b_hb, dA, (float*)d_out, nullptr, M, 1);
    }
}